// round 12
// baseline (speedup 1.0000x reference)
#include <cuda_runtime.h>
#include <cstdint>

// ---------------------------------------------------------------------------
// Transformer block — all GEMMs int8 2-limb IMMA (q = 256h + l, 15-bit).
// R12: quantization fused into producing epilogues with per-128-block scales;
// consumers fold block scales per k-slab (512-thr gemm_i8_blk). Attention
// stays bf16x3 HMMA. B=384, S=128, E=512, H=4, D=128, F=2048.
// ---------------------------------------------------------------------------

constexpr int Bb = 384, Ss = 128, Ee = 512, Ff = 2048;
constexpr int MM = Bb * Ss, NQKV = 3 * Ee;

__device__ int8_t   g_xqh [(size_t)MM * Ee],  g_xql [(size_t)MM * Ee];
__device__ float    g_sx[MM];
__device__ uint16_t g_qh [(size_t)MM * NQKV], g_ql [(size_t)MM * NQKV];
__device__ int8_t   g_atqh[(size_t)MM * Ee],  g_atql[(size_t)MM * Ee];
__device__ float    g_sat[(size_t)MM * 4];
__device__ float    g_x1f[(size_t)MM * Ee];
__device__ int8_t   g_x1qh[(size_t)MM * Ee],  g_x1ql[(size_t)MM * Ee];
__device__ float    g_sx1[MM];
__device__ int8_t   g_hqh [(size_t)MM * Ff],  g_hql [(size_t)MM * Ff];
__device__ float    g_sh[(size_t)MM * 16];
__device__ int8_t   g_wqkvqh[(size_t)NQKV * Ee], g_wqkvql[(size_t)NQKV * Ee];
__device__ float    g_swqkv[NQKV];
__device__ int8_t   g_woqh[(size_t)Ee * Ee],  g_woql[(size_t)Ee * Ee];
__device__ float    g_swo[Ee];
__device__ int8_t   g_w1qh[(size_t)Ff * Ee],  g_w1ql[(size_t)Ff * Ee];
__device__ float    g_sw1[Ff];
__device__ int8_t   g_w2qh[(size_t)Ee * Ff],  g_w2ql[(size_t)Ee * Ff];
__device__ float    g_sw2[Ee];
__device__ float    g_bqkv[NQKV];

__device__ __forceinline__ void split2(float v, uint16_t& h, uint16_t& l) {
    float hf;
    asm("cvt.rn.bf16.f32 %0, %1;" : "=h"(h) : "f"(v));
    asm("cvt.f32.bf16 %0, %1;"    : "=f"(hf) : "h"(h));
    asm("cvt.rn.bf16.f32 %0, %1;" : "=h"(l) : "f"(v - hf));
}
__device__ __forceinline__ uint32_t cvta_s(const void* p) {
    uint32_t a;
    asm("{\n\t.reg .u64 t;\n\tcvta.to.shared.u64 t, %1;\n\tcvt.u32.u64 %0, t;\n\t}"
        : "=r"(a) : "l"(p));
    return a;
}
#define CP16(s, g)  asm volatile("cp.async.cg.shared.global [%0], [%1], 16;" ::"r"(s), "l"(g))
#define CPCOMMIT()  asm volatile("cp.async.commit_group;" ::: "memory")
__device__ __forceinline__ void cpwait(int n) {
    if (n >= 2)      asm volatile("cp.async.wait_group 2;" ::: "memory");
    else if (n == 1) asm volatile("cp.async.wait_group 1;" ::: "memory");
    else             asm volatile("cp.async.wait_group 0;" ::: "memory");
}
#define LDSM4(r0, r1, r2, r3, a) \
    asm volatile("ldmatrix.sync.aligned.m8n8.x4.shared.b16 {%0,%1,%2,%3}, [%4];" \
        : "=r"(r0), "=r"(r1), "=r"(r2), "=r"(r3) : "r"(a))
#define LDSM4T(r0, r1, r2, r3, a) \
    asm volatile("ldmatrix.sync.aligned.m8n8.x4.trans.shared.b16 {%0,%1,%2,%3}, [%4];" \
        : "=r"(r0), "=r"(r1), "=r"(r2), "=r"(r3) : "r"(a))
#define STS32(a, v) asm volatile("st.shared.b32 [%0], %1;" ::"r"(a), "r"(v) : "memory")

__device__ __forceinline__ void mma16(float* d, const uint32_t* a,
                                      uint32_t b0, uint32_t b1) {
    asm("mma.sync.aligned.m16n8k16.row.col.f32.bf16.bf16.f32 "
        "{%0,%1,%2,%3}, {%4,%5,%6,%7}, {%8,%9}, {%0,%1,%2,%3};\n"
        : "+f"(d[0]), "+f"(d[1]), "+f"(d[2]), "+f"(d[3])
        : "r"(a[0]), "r"(a[1]), "r"(a[2]), "r"(a[3]), "r"(b0), "r"(b1));
}
__device__ __forceinline__ void mma3(float* d, const uint32_t* ah, const uint32_t* al,
                                     uint32_t bh0, uint32_t bh1,
                                     uint32_t bl0, uint32_t bl1) {
    mma16(d, ah, bh0, bh1);
    mma16(d, al, bh0, bh1);
    mma16(d, ah, bl0, bl1);
}
__device__ __forceinline__ void imma32(int* d, const uint32_t* a,
                                       uint32_t b0, uint32_t b1) {
    asm("mma.sync.aligned.m16n8k32.row.col.s32.s8.s8.s32 "
        "{%0,%1,%2,%3}, {%4,%5,%6,%7}, {%8,%9}, {%0,%1,%2,%3};\n"
        : "+r"(d[0]), "+r"(d[1]), "+r"(d[2]), "+r"(d[3])
        : "r"(a[0]), "r"(a[1]), "r"(a[2]), "r"(a[3]), "r"(b0), "r"(b1));
}
__device__ __forceinline__ void imma32_z(int* d, const uint32_t* a,
                                         uint32_t b0, uint32_t b1) {
    asm("mma.sync.aligned.m16n8k32.row.col.s32.s8.s8.s32 "
        "{%0,%1,%2,%3}, {%4,%5,%6,%7}, {%8,%9}, {%10,%10,%10,%10};\n"
        : "=r"(d[0]), "=r"(d[1]), "=r"(d[2]), "=r"(d[3])
        : "r"(a[0]), "r"(a[1]), "r"(a[2]), "r"(a[3]), "r"(b0), "r"(b1), "r"(0));
}
__device__ __forceinline__ void q2limb(float v, float inv, int& h, int& l) {
    const int q = (int)rintf(v * inv);
    h = (q + 128) >> 8;
    l = q - (h << 8);
}

// ---------------------------------------------------------------------------
// prep: bias concat + int8 quant of all weights (per-out-col scale, [N][K])
// ---------------------------------------------------------------------------
__global__ void prep_all(const float* __restrict__ bq, const float* __restrict__ bk,
                         const float* __restrict__ bv,
                         const float* __restrict__ wq, const float* __restrict__ wk,
                         const float* __restrict__ wv, const float* __restrict__ wo,
                         const float* __restrict__ w1, const float* __restrict__ w2) {
    __shared__ uint32_t tile[32][33];
    __shared__ float smax[8][32];
    const int bidx = blockIdx.x;
    const int lx = threadIdx.x & 31, ly = threadIdx.x >> 5;
    if (bidx < 6) {
        const int i = bidx * 256 + threadIdx.x;
        if (i < NQKV)
            g_bqkv[i] = i < 512 ? bq[i] : (i < 1024 ? bk[i - 512] : bv[i - 1024]);
        return;
    }
    const int id = bidx - 6;
    const float* W; int8_t *Qh, *Ql; float* Sd;
    int Nsrc, K, nb, srccol, destrow;
    if (id < 48) {
        nb = id * 32;
        W = nb < 512 ? wq : (nb < 1024 ? wk : wv);
        srccol = nb & 511; destrow = nb;
        Qh = g_wqkvqh; Ql = g_wqkvql; Sd = g_swqkv; Nsrc = 512; K = 512;
    } else if (id < 64) {
        nb = (id - 48) * 32; srccol = nb; destrow = nb;
        W = wo; Qh = g_woqh; Ql = g_woql; Sd = g_swo; Nsrc = 512; K = 512;
    } else if (id < 128) {
        nb = (id - 64) * 32; srccol = nb; destrow = nb;
        W = w1; Qh = g_w1qh; Ql = g_w1ql; Sd = g_sw1; Nsrc = 2048; K = 512;
    } else {
        nb = (id - 128) * 32; srccol = nb; destrow = nb;
        W = w2; Qh = g_w2qh; Ql = g_w2ql; Sd = g_sw2; Nsrc = 512; K = 2048;
    }
    float mx = 0.f;
    for (int k = ly; k < K; k += 8)
        mx = fmaxf(mx, fabsf(W[(size_t)k * Nsrc + srccol + lx]));
    smax[ly][lx] = mx;
    __syncthreads();
    if (ly == 0) {
        for (int i = 1; i < 8; i++) mx = fmaxf(mx, smax[i][lx]);
        const float d = mx > 0.f ? mx * (1.f / 32639.f) : 1.f;
        smax[0][lx] = 1.f / d;
        Sd[destrow + lx] = d;
    }
    __syncthreads();
    const float inv = smax[0][lx];
    for (int kb = 0; kb < K; kb += 32) {
        for (int j = ly; j < 32; j += 8) {
            int h, l;
            q2limb(W[(size_t)(kb + j) * Nsrc + srccol + lx], inv, h, l);
            tile[j][lx] = (uint32_t)(uint8_t)h | ((uint32_t)(uint8_t)l << 8);
        }
        __syncthreads();
        for (int j = ly; j < 32; j += 8) {
            const uint32_t t = tile[lx][j];
            const size_t o = (size_t)(destrow + j) * K + kb + lx;
            Qh[o] = (int8_t)(t & 255);
            Ql[o] = (int8_t)((t >> 8) & 255);
        }
        __syncthreads();
    }
}

// quant_rows: per-row scale (x, x1)
template <int KQ>
__global__ __launch_bounds__(256)
void quant_rows(const float* __restrict__ src, int8_t* __restrict__ qh,
                int8_t* __restrict__ ql, float* __restrict__ sc) {
    const int w = threadIdx.x >> 5, lane = threadIdx.x & 31;
    const int row = blockIdx.x * 8 + w;
    const float* s = src + (size_t)row * KQ;
    constexpr int J = KQ / 128;
    float4 v[J];
    float mx = 0.f;
#pragma unroll
    for (int j = 0; j < J; j++) {
        v[j] = *(const float4*)(s + j * 128 + lane * 4);
        mx = fmaxf(mx, fmaxf(fmaxf(fabsf(v[j].x), fabsf(v[j].y)),
                             fmaxf(fabsf(v[j].z), fabsf(v[j].w))));
    }
#pragma unroll
    for (int o = 16; o; o >>= 1) mx = fmaxf(mx, __shfl_xor_sync(0xffffffffu, mx, o));
    const float d = mx > 0.f ? mx * (1.f / 32639.f) : 1.f;
    const float inv = 1.f / d;
    if (lane == 0) sc[row] = d;
#pragma unroll
    for (int j = 0; j < J; j++) {
        int h0, l0, h1, l1, h2, l2, h3, l3;
        q2limb(v[j].x, inv, h0, l0); q2limb(v[j].y, inv, h1, l1);
        q2limb(v[j].z, inv, h2, l2); q2limb(v[j].w, inv, h3, l3);
        *(uint32_t*)(qh + (size_t)row * KQ + j * 128 + lane * 4) =
            (h0 & 255) | ((h1 & 255) << 8) | ((h2 & 255) << 16) | ((h3 & 255) << 24);
        *(uint32_t*)(ql + (size_t)row * KQ + j * 128 + lane * 4) =
            (l0 & 255) | ((l1 & 255) << 8) | ((l2 & 255) << 16) | ((l3 & 255) << 24);
    }
}

// ---------------------------------------------------------------------------
// gemm_i8 (256 thr, row-scale A, full-K s32 accumulation, K=512 only)
// EPI 0: relu + fused quant -> limbs + per-(row,128-block) scale
// EPI 2: bf16 planes (QKV)
// ---------------------------------------------------------------------------
constexpr int I8_STGB = 65536;
constexpr int SMEM_I8 = 3 * I8_STGB;

template <int EPI>
__global__ __launch_bounds__(256, 1)
void gemm_i8(const int8_t* __restrict__ Ah_, const int8_t* __restrict__ Al_,
             const int8_t* __restrict__ Bh_, const int8_t* __restrict__ Bl_,
             const float* __restrict__ sa, const float* __restrict__ sb,
             const float* __restrict__ bias,
             uint16_t* __restrict__ Ph, uint16_t* __restrict__ Pl,
             int8_t* __restrict__ Qh, int8_t* __restrict__ Ql,
             float* __restrict__ scOut, int Nout, int K) {
    extern __shared__ char smraw[];
    const uint32_t sbase = cvta_s(smraw);
    const int tid = threadIdx.x, wid = tid >> 5, lane = tid & 31;
    const int wm = wid >> 2, wn = wid & 3;
    const int mB = blockIdx.y * 128, nB = blockIdx.x * 128;
    const int l7 = lane & 7, l8 = (lane >> 3) & 1, l16 = lane >> 4;

    const int trow = tid >> 3, tch = tid & 7;
    const uint32_t dst0 = trow * 128 + (((uint32_t)tch ^ (trow & 7)) << 4);
    const int8_t* bp[4];
    bp[0] = Ah_ + (size_t)(mB + trow) * K + tch * 16;
    bp[1] = Al_ + (size_t)(mB + trow) * K + tch * 16;
    bp[2] = Bh_ + (size_t)(nB + trow) * K + tch * 16;
    bp[3] = Bl_ + (size_t)(nB + trow) * K + tch * 16;

    int hh[4][4][4], cr[4][4][4];
#pragma unroll
    for (int a = 0; a < 4; a++)
#pragma unroll
        for (int b = 0; b < 4; b++)
#pragma unroll
            for (int c = 0; c < 4; c++) { hh[a][b][c] = 0; cr[a][b][c] = 0; }

    auto issue = [&](int s) {
        const uint32_t stb = sbase + (s % 3) * I8_STGB;
        const int kg = s * 128;
#pragma unroll
        for (int pl = 0; pl < 4; pl++) {
            const int8_t* gp = bp[pl] + kg;
#pragma unroll
            for (int i2 = 0; i2 < 4; i2++)
                CP16(stb + pl * 16384 + dst0 + i2 * 4096, gp + (size_t)i2 * 32 * K);
        }
        CPCOMMIT();
    };

    const int nT = K >> 7;
    issue(0);
    if (nT > 1) issue(1);

    const uint32_t raBase[4] = {
        (uint32_t)(wm * 64 + 0 + l8 * 8 + l7),  (uint32_t)(wm * 64 + 16 + l8 * 8 + l7),
        (uint32_t)(wm * 64 + 32 + l8 * 8 + l7), (uint32_t)(wm * 64 + 48 + l8 * 8 + l7)};
    const uint32_t rbBase[2] = {
        (uint32_t)(wn * 32 + l8 * 8 + l7), (uint32_t)(wn * 32 + 16 + l8 * 8 + l7)};

    for (int t = 0; t < nT; t++) {
        cpwait(t < nT - 1 ? 1 : 0);
        __syncthreads();
        if (t + 2 < nT) issue(t + 2);
        const uint32_t stb = sbase + (t % 3) * I8_STGB;
#pragma unroll
        for (int b = 0; b < 4; b++) {
            uint32_t ahf[4][4], alf[4][4];
#pragma unroll
            for (int mi = 0; mi < 4; mi++) {
                const uint32_t r = raBase[mi];
                const uint32_t base = stb + r * 128;
                const uint32_t ch = (uint32_t)((2 * b + l16) ^ (r & 7)) << 4;
                LDSM4(ahf[mi][0], ahf[mi][1], ahf[mi][2], ahf[mi][3], base + ch);
                LDSM4(alf[mi][0], alf[mi][1], alf[mi][2], alf[mi][3], base + 16384 + ch);
            }
#pragma unroll
            for (int j2 = 0; j2 < 2; j2++) {
                const uint32_t r = rbBase[j2];
                const uint32_t baseB = stb + 32768 + r * 128;
                const uint32_t ch = (uint32_t)((2 * b + l16) ^ (r & 7)) << 4;
                uint32_t bh0, bh1, bh2, bh3, bl0, bl1, bl2, bl3;
                LDSM4(bh0, bh1, bh2, bh3, baseB + ch);
                LDSM4(bl0, bl1, bl2, bl3, baseB + 16384 + ch);
#pragma unroll
                for (int mi = 0; mi < 4; mi++) {
                    imma32(hh[mi][2 * j2],     ahf[mi], bh0, bh2);
                    imma32(hh[mi][2 * j2 + 1], ahf[mi], bh1, bh3);
                    imma32(cr[mi][2 * j2],     ahf[mi], bl0, bl2);
                    imma32(cr[mi][2 * j2 + 1], ahf[mi], bl1, bl3);
                    imma32(cr[mi][2 * j2],     alf[mi], bh0, bh2);
                    imma32(cr[mi][2 * j2 + 1], alf[mi], bh1, bh3);
                }
            }
        }
    }

    if (EPI == 2) {
#pragma unroll
        for (int mi = 0; mi < 4; mi++) {
            const int r0 = mB + wm * 64 + mi * 16 + (lane >> 2);
            const int r1 = r0 + 8;
            const float sa0 = sa[r0], sa1 = sa[r1];
#pragma unroll
            for (int nj = 0; nj < 4; nj++) {
                const int c = nB + wn * 32 + nj * 8 + 2 * (lane & 3);
                const float sb0 = sb[c], sb1 = sb[c + 1];
                const float b0 = bias[c], b1v = bias[c + 1];
                const float v0 = ((float)hh[mi][nj][0] * 65536.f + (float)cr[mi][nj][0] * 256.f) * (sa0 * sb0) + b0;
                const float v1 = ((float)hh[mi][nj][1] * 65536.f + (float)cr[mi][nj][1] * 256.f) * (sa0 * sb1) + b1v;
                const float v2 = ((float)hh[mi][nj][2] * 65536.f + (float)cr[mi][nj][2] * 256.f) * (sa1 * sb0) + b0;
                const float v3 = ((float)hh[mi][nj][3] * 65536.f + (float)cr[mi][nj][3] * 256.f) * (sa1 * sb1) + b1v;
                uint16_t h0, l0, h1, l1;
                split2(v0, h0, l0); split2(v1, h1, l1);
                *(uint32_t*)(Ph + (size_t)r0 * Nout + c) = (uint32_t)h0 | ((uint32_t)h1 << 16);
                *(uint32_t*)(Pl + (size_t)r0 * Nout + c) = (uint32_t)l0 | ((uint32_t)l1 << 16);
                split2(v2, h0, l0); split2(v3, h1, l1);
                *(uint32_t*)(Ph + (size_t)r1 * Nout + c) = (uint32_t)h0 | ((uint32_t)h1 << 16);
                *(uint32_t*)(Pl + (size_t)r1 * Nout + c) = (uint32_t)l0 | ((uint32_t)l1 << 16);
            }
        }
    } else {
        // EPI 0: relu + fused quant with per-(row, 128-block) scale
        __syncthreads();
        float* rmax = (float*)smraw;       // [128][4]
        const int q4 = lane & 3, g8 = lane >> 2;
#pragma unroll
        for (int mi = 0; mi < 4; mi++) {
            const int lr0 = wm * 64 + mi * 16 + g8;
            const float sa0 = sa[mB + lr0], sa1 = sa[mB + lr0 + 8];
            float m0 = 0.f, m1 = 0.f;
#pragma unroll
            for (int nj = 0; nj < 4; nj++) {
                const int c = nB + wn * 32 + nj * 8 + 2 * q4;
                const float sb0 = sb[c], sb1 = sb[c + 1];
                const float b0 = bias[c], b1v = bias[c + 1];
                const float v0 = fmaxf(((float)hh[mi][nj][0] * 65536.f + (float)cr[mi][nj][0] * 256.f) * (sa0 * sb0) + b0, 0.f);
                const float v1 = fmaxf(((float)hh[mi][nj][1] * 65536.f + (float)cr[mi][nj][1] * 256.f) * (sa0 * sb1) + b1v, 0.f);
                const float v2 = fmaxf(((float)hh[mi][nj][2] * 65536.f + (float)cr[mi][nj][2] * 256.f) * (sa1 * sb0) + b0, 0.f);
                const float v3 = fmaxf(((float)hh[mi][nj][3] * 65536.f + (float)cr[mi][nj][3] * 256.f) * (sa1 * sb1) + b1v, 0.f);
                m0 = fmaxf(m0, fmaxf(v0, v1));
                m1 = fmaxf(m1, fmaxf(v2, v3));
            }
            m0 = fmaxf(m0, __shfl_xor_sync(0xffffffffu, m0, 1));
            m0 = fmaxf(m0, __shfl_xor_sync(0xffffffffu, m0, 2));
            m1 = fmaxf(m1, __shfl_xor_sync(0xffffffffu, m1, 1));
            m1 = fmaxf(m1, __shfl_xor_sync(0xffffffffu, m1, 2));
            if (q4 == 0) {
                rmax[lr0 * 4 + wn] = m0;
                rmax[(lr0 + 8) * 4 + wn] = m1;
            }
        }
        __syncthreads();
        const int nblkO = Nout >> 7;
#pragma unroll
        for (int mi = 0; mi < 4; mi++) {
            const int lr0 = wm * 64 + mi * 16 + g8;
            const int grow0 = mB + lr0, grow1 = grow0 + 8;
            const float M0 = fmaxf(fmaxf(rmax[lr0 * 4], rmax[lr0 * 4 + 1]),
                                   fmaxf(rmax[lr0 * 4 + 2], rmax[lr0 * 4 + 3]));
            const float M1 = fmaxf(fmaxf(rmax[(lr0 + 8) * 4], rmax[(lr0 + 8) * 4 + 1]),
                                   fmaxf(rmax[(lr0 + 8) * 4 + 2], rmax[(lr0 + 8) * 4 + 3]));
            const float d0 = M0 > 0.f ? M0 * (1.f / 32639.f) : 1.f;
            const float d1 = M1 > 0.f ? M1 * (1.f / 32639.f) : 1.f;
            const float i0 = 1.f / d0, i1 = 1.f / d1;
            if (wn == 0 && q4 == 0) {
                scOut[(size_t)grow0 * nblkO + blockIdx.x] = d0;
                scOut[(size_t)grow1 * nblkO + blockIdx.x] = d1;
            }
            const float sa0 = sa[grow0], sa1 = sa[grow1];
#pragma unroll
            for (int nj = 0; nj < 4; nj++) {
                const int c = nB + wn * 32 + nj * 8 + 2 * q4;
                const float sb0 = sb[c], sb1 = sb[c + 1];
                const float b0 = bias[c], b1v = bias[c + 1];
                const float v0 = fmaxf(((float)hh[mi][nj][0] * 65536.f + (float)cr[mi][nj][0] * 256.f) * (sa0 * sb0) + b0, 0.f);
                const float v1 = fmaxf(((float)hh[mi][nj][1] * 65536.f + (float)cr[mi][nj][1] * 256.f) * (sa0 * sb1) + b1v, 0.f);
                const float v2 = fmaxf(((float)hh[mi][nj][2] * 65536.f + (float)cr[mi][nj][2] * 256.f) * (sa1 * sb0) + b0, 0.f);
                const float v3 = fmaxf(((float)hh[mi][nj][3] * 65536.f + (float)cr[mi][nj][3] * 256.f) * (sa1 * sb1) + b1v, 0.f);
                int h0, l0, h1, l1;
                q2limb(v0, i0, h0, l0); q2limb(v1, i0, h1, l1);
                *(uint16_t*)(Qh + (size_t)grow0 * Nout + c) = (uint16_t)((h0 & 255) | ((h1 & 255) << 8));
                *(uint16_t*)(Ql + (size_t)grow0 * Nout + c) = (uint16_t)((l0 & 255) | ((l1 & 255) << 8));
                q2limb(v2, i1, h0, l0); q2limb(v3, i1, h1, l1);
                *(uint16_t*)(Qh + (size_t)grow1 * Nout + c) = (uint16_t)((h0 & 255) | ((h1 & 255) << 8));
                *(uint16_t*)(Ql + (size_t)grow1 * Nout + c) = (uint16_t)((l0 & 255) | ((l1 & 255) << 8));
            }
        }
    }
}

// ---------------------------------------------------------------------------
// gemm_i8_blk (512 thr): A has per-(row, k-block-128) scales; per-block s32
// accumulation folded into fp32. out = accf*sb + bias + res (f32).
// Tile 128x128, warp grid 2(M)x8(N), warp tile 64x16.
// ---------------------------------------------------------------------------
__global__ __launch_bounds__(512, 1)
void gemm_i8_blk(const int8_t* __restrict__ Ah_, const int8_t* __restrict__ Al_,
                 const int8_t* __restrict__ Bh_, const int8_t* __restrict__ Bl_,
                 const float* __restrict__ sa, const float* __restrict__ sb,
                 const float* __restrict__ bias, const float* __restrict__ res,
                 float* __restrict__ out, int Nout, int K) {
    extern __shared__ char smraw[];
    const uint32_t sbase = cvta_s(smraw);
    const int tid = threadIdx.x, wid = tid >> 5, lane = tid & 31;
    const int wm = wid >> 3, wn = wid & 7;
    const int mB = blockIdx.y * 128, nB = blockIdx.x * 128;
    const int l7 = lane & 7, l8 = (lane >> 3) & 1, l16 = lane >> 4;
    const int nblk = K >> 7;

    const int trow = tid >> 3, tch = tid & 7;   // trow 0..63
    const uint32_t dst0 = trow * 128 + (((uint32_t)tch ^ (trow & 7)) << 4);
    const int8_t* bp[4];
    bp[0] = Ah_ + (size_t)(mB + trow) * K + tch * 16;
    bp[1] = Al_ + (size_t)(mB + trow) * K + tch * 16;
    bp[2] = Bh_ + (size_t)(nB + trow) * K + tch * 16;
    bp[3] = Bl_ + (size_t)(nB + trow) * K + tch * 16;

    float accf[4][2][4];
#pragma unroll
    for (int a = 0; a < 4; a++)
#pragma unroll
        for (int b = 0; b < 2; b++)
#pragma unroll
            for (int c = 0; c < 4; c++) accf[a][b][c] = 0.f;

    auto issue = [&](int s) {
        const uint32_t stb = sbase + (s % 3) * I8_STGB;
        const int kg = s * 128;
#pragma unroll
        for (int pl = 0; pl < 4; pl++) {
            const int8_t* gp = bp[pl] + kg;
#pragma unroll
            for (int i2 = 0; i2 < 2; i2++)
                CP16(stb + pl * 16384 + dst0 + i2 * 8192, gp + (size_t)i2 * 64 * K);
        }
        CPCOMMIT();
    };

    const int nT = K >> 7;
    issue(0);
    if (nT > 1) issue(1);

    const uint32_t raBase[4] = {
        (uint32_t)(wm * 64 + 0 + l8 * 8 + l7),  (uint32_t)(wm * 64 + 16 + l8 * 8 + l7),
        (uint32_t)(wm * 64 + 32 + l8 * 8 + l7), (uint32_t)(wm * 64 + 48 + l8 * 8 + l7)};
    const uint32_t rbB = (uint32_t)(wn * 16 + l8 * 8 + l7);

    for (int t = 0; t < nT; t++) {
        cpwait(t < nT - 1 ? 1 : 0);
        __syncthreads();
        if (t + 2 < nT) issue(t + 2);
        const uint32_t stb = sbase + (t % 3) * I8_STGB;

        int hh[4][2][4], cr[4][2][4];
#pragma unroll
        for (int b = 0; b < 4; b++) {
            uint32_t ahf[4][4], alf[4][4];
#pragma unroll
            for (int mi = 0; mi < 4; mi++) {
                const uint32_t r = raBase[mi];
                const uint32_t base = stb + r * 128;
                const uint32_t ch = (uint32_t)((2 * b + l16) ^ (r & 7)) << 4;
                LDSM4(ahf[mi][0], ahf[mi][1], ahf[mi][2], ahf[mi][3], base + ch);
                LDSM4(alf[mi][0], alf[mi][1], alf[mi][2], alf[mi][3], base + 16384 + ch);
            }
            const uint32_t baseB = stb + 32768 + rbB * 128;
            const uint32_t chB = (uint32_t)((2 * b + l16) ^ (rbB & 7)) << 4;
            uint32_t bh0, bh1, bh2, bh3, bl0, bl1, bl2, bl3;
            LDSM4(bh0, bh1, bh2, bh3, baseB + chB);
            LDSM4(bl0, bl1, bl2, bl3, baseB + 16384 + chB);
            if (b == 0) {
#pragma unroll
                for (int mi = 0; mi < 4; mi++) {
                    imma32_z(hh[mi][0], ahf[mi], bh0, bh2);
                    imma32_z(hh[mi][1], ahf[mi], bh1, bh3);
                    imma32_z(cr[mi][0], ahf[mi], bl0, bl2);
                    imma32_z(cr[mi][1], ahf[mi], bl1, bl3);
                    imma32(cr[mi][0], alf[mi], bh0, bh2);
                    imma32(cr[mi][1], alf[mi], bh1, bh3);
                }
            } else {
#pragma unroll
                for (int mi = 0; mi < 4; mi++) {
                    imma32(hh[mi][0], ahf[mi], bh0, bh2);
                    imma32(hh[mi][1], ahf[mi], bh1, bh3);
                    imma32(cr[mi][0], ahf[mi], bl0, bl2);
                    imma32(cr[mi][1], ahf[mi], bl1, bl3);
                    imma32(cr[mi][0], alf[mi], bh0, bh2);
                    imma32(cr[mi][1], alf[mi], bh1, bh3);
                }
            }
        }
        // fold block t with per-(row, t) A scale
#pragma unroll
        for (int mi = 0; mi < 4; mi++) {
            const int r0 = mB + wm * 64 + mi * 16 + (lane >> 2);
            const float sa0 = __ldg(sa + (size_t)r0 * nblk + t);
            const float sa1 = __ldg(sa + (size_t)(r0 + 8) * nblk + t);
#pragma unroll
            for (int nj = 0; nj < 2; nj++) {
                accf[mi][nj][0] += ((float)hh[mi][nj][0] * 65536.f + (float)cr[mi][nj][0] * 256.f) * sa0;
                accf[mi][nj][1] += ((float)hh[mi][nj][1] * 65536.f + (float)cr[mi][nj][1] * 256.f) * sa0;
                accf[mi][nj][2] += ((float)hh[mi][nj][2] * 65536.f + (float)cr[mi][nj][2] * 256.f) * sa1;
                accf[mi][nj][3] += ((float)hh[mi][nj][3] * 65536.f + (float)cr[mi][nj][3] * 256.f) * sa1;
            }
        }
    }

#pragma unroll
    for (int mi = 0; mi < 4; mi++) {
        const int r0 = mB + wm * 64 + mi * 16 + (lane >> 2);
        const int r1 = r0 + 8;
#pragma unroll
        for (int nj = 0; nj < 2; nj++) {
            const int c = nB + wn * 16 + nj * 8 + 2 * (lane & 3);
            const float sb0 = sb[c], sb1 = sb[c + 1];
            const float b0 = bias[c], b1v = bias[c + 1];
            const float2 rv0 = *(const float2*)(res + (size_t)r0 * Nout + c);
            const float2 rv1 = *(const float2*)(res + (size_t)r1 * Nout + c);
            *(float2*)(out + (size_t)r0 * Nout + c) =
                make_float2(accf[mi][nj][0] * sb0 + b0 + rv0.x,
                            accf[mi][nj][1] * sb1 + b1v + rv0.y);
            *(float2*)(out + (size_t)r1 * Nout + c) =
                make_float2(accf[mi][nj][2] * sb0 + b0 + rv1.x,
                            accf[mi][nj][3] * sb1 + b1v + rv1.y);
        }
    }
}

// ---------------------------------------------------------------------------
// Attention (bf16x3) — epilogue quantizes per-(row, head) directly.
// ---------------------------------------------------------------------------
constexpr int SMEM_ATTN = 6 * 32768;

__global__ __launch_bounds__(256, 1)
void attn_kernel(const uint16_t* __restrict__ qh, const uint16_t* __restrict__ ql,
                 int8_t* __restrict__ Oqh, int8_t* __restrict__ Oql,
                 float* __restrict__ Osc) {
    extern __shared__ char smraw[];
    const uint32_t sb = cvta_s(smraw);
    const uint32_t QH = sb, QL = sb + 32768, KH = sb + 65536, KL = sb + 98304;
    const uint32_t VH = sb + 131072, VL = sb + 163840;

    const int tid = threadIdx.x, bh = blockIdx.x;
    const int bb = bh >> 2, head = bh & 3;
    const size_t rowbase = (size_t)bb * Ss * NQKV;
    const int coloff = head * 128;

#pragma unroll
    for (int i = 0; i < 48; i++) {
        const int idx = tid + i * 256;
        const int p = idx >> 11, rem = idx & 2047;
        const int row = rem >> 4, c = rem & 15;
        const uint16_t* base = (p & 1) ? ql : qh;
        const size_t src = rowbase + (size_t)row * NQKV + (p >> 1) * 512 + coloff + c * 8;
        CP16(sb + p * 32768 + row * 256 + ((uint32_t)(c ^ (row & 7)) << 4), base + src);
    }
    CPCOMMIT();
    cpwait(0);
    __syncthreads();

    const int wid = tid >> 5, lane = tid & 31;
    const int g = lane >> 2, q = lane & 3;
    const int l7 = lane & 7, l8 = (lane >> 3) & 1, l16 = lane >> 4;
    const int rbase = wid * 16;
    const int ra = rbase + l8 * 8 + l7;

    float acc[16][4];
#pragma unroll
    for (int j = 0; j < 16; j++)
#pragma unroll
        for (int c = 0; c < 4; c++) acc[j][c] = 0.f;

#pragma unroll
    for (int kk = 0; kk < 8; kk++) {
        const uint32_t ca = ((uint32_t)((2 * kk + l16) ^ (ra & 7)) << 4) + ra * 256;
        uint32_t ah[4], al[4];
        LDSM4(ah[0], ah[1], ah[2], ah[3], QH + ca);
        LDSM4(al[0], al[1], al[2], al[3], QL + ca);
#pragma unroll
        for (int j2 = 0; j2 < 8; j2++) {
            const int rb = j2 * 16 + l8 * 8 + l7;
            const uint32_t cb = ((uint32_t)((2 * kk + l16) ^ (rb & 7)) << 4) + rb * 256;
            uint32_t bh_[4], bl_[4];
            LDSM4(bh_[0], bh_[1], bh_[2], bh_[3], KH + cb);
            LDSM4(bl_[0], bl_[1], bl_[2], bl_[3], KL + cb);
            mma3(acc[j2 * 2],     ah, al, bh_[0], bh_[2], bl_[0], bl_[2]);
            mma3(acc[j2 * 2 + 1], ah, al, bh_[1], bh_[3], bl_[1], bl_[3]);
        }
    }

    float m0 = -1e30f, m1 = -1e30f;
#pragma unroll
    for (int j = 0; j < 16; j++) {
        m0 = fmaxf(m0, fmaxf(acc[j][0], acc[j][1]));
        m1 = fmaxf(m1, fmaxf(acc[j][2], acc[j][3]));
    }
    m0 = fmaxf(m0, __shfl_xor_sync(0xffffffffu, m0, 1));
    m0 = fmaxf(m0, __shfl_xor_sync(0xffffffffu, m0, 2));
    m1 = fmaxf(m1, __shfl_xor_sync(0xffffffffu, m1, 1));
    m1 = fmaxf(m1, __shfl_xor_sync(0xffffffffu, m1, 2));
    float s0 = 0.f, s1 = 0.f;
#pragma unroll
    for (int j = 0; j < 16; j++) {
        acc[j][0] = expf(acc[j][0] - m0);
        acc[j][1] = expf(acc[j][1] - m0);
        acc[j][2] = expf(acc[j][2] - m1);
        acc[j][3] = expf(acc[j][3] - m1);
        s0 += acc[j][0] + acc[j][1];
        s1 += acc[j][2] + acc[j][3];
    }
    s0 += __shfl_xor_sync(0xffffffffu, s0, 1);
    s0 += __shfl_xor_sync(0xffffffffu, s0, 2);
    s1 += __shfl_xor_sync(0xffffffffu, s1, 1);
    s1 += __shfl_xor_sync(0xffffffffu, s1, 2);
    const float r0s = 1.f / s0, r1s = 1.f / s1;

    const int pr0 = rbase + g, pr1 = pr0 + 8;
#pragma unroll
    for (int j = 0; j < 16; j++) {
        const uint32_t off0 = pr0 * 256 + ((uint32_t)(j ^ (pr0 & 7)) << 4) + 4 * q;
        const uint32_t off1 = pr1 * 256 + ((uint32_t)(j ^ (pr1 & 7)) << 4) + 4 * q;
        uint16_t h0, l0, h1, l1;
        split2(acc[j][0] * r0s, h0, l0); split2(acc[j][1] * r0s, h1, l1);
        STS32(QH + off0, (uint32_t)h0 | ((uint32_t)h1 << 16));
        STS32(QL + off0, (uint32_t)l0 | ((uint32_t)l1 << 16));
        split2(acc[j][2] * r1s, h0, l0); split2(acc[j][3] * r1s, h1, l1);
        STS32(QH + off1, (uint32_t)h0 | ((uint32_t)h1 << 16));
        STS32(QL + off1, (uint32_t)l0 | ((uint32_t)l1 << 16));
    }
    __syncwarp();

    float acc2[16][4];
#pragma unroll
    for (int j = 0; j < 16; j++)
#pragma unroll
        for (int c = 0; c < 4; c++) acc2[j][c] = 0.f;

#pragma unroll
    for (int kk = 0; kk < 8; kk++) {
        const uint32_t ca = ((uint32_t)((2 * kk + l16) ^ (ra & 7)) << 4) + ra * 256;
        uint32_t ah[4], al[4];
        LDSM4(ah[0], ah[1], ah[2], ah[3], QH + ca);
        LDSM4(al[0], al[1], al[2], al[3], QL + ca);
        const int krow = kk * 16 + l8 * 8 + l7;
#pragma unroll
        for (int j2 = 0; j2 < 8; j2++) {
            const int cj = j2 * 2 + l16;
            const uint32_t cb = ((uint32_t)(cj ^ (krow & 7)) << 4) + krow * 256;
            uint32_t vh_[4], vl_[4];
            LDSM4T(vh_[0], vh_[1], vh_[2], vh_[3], VH + cb);
            LDSM4T(vl_[0], vl_[1], vl_[2], vl_[3], VL + cb);
            mma3(acc2[j2 * 2],     ah, al, vh_[0], vh_[1], vl_[0], vl_[1]);
            mma3(acc2[j2 * 2 + 1], ah, al, vh_[2], vh_[3], vl_[2], vl_[3]);
        }
    }

    // fused quant epilogue: per-(row, head) scale, limbs out
    const int grow0 = bb * Ss + pr0, grow1 = grow0 + 8;
    float a0 = 0.f, a1 = 0.f;
#pragma unroll
    for (int j = 0; j < 16; j++) {
        a0 = fmaxf(a0, fmaxf(fabsf(acc2[j][0]), fabsf(acc2[j][1])));
        a1 = fmaxf(a1, fmaxf(fabsf(acc2[j][2]), fabsf(acc2[j][3])));
    }
    a0 = fmaxf(a0, __shfl_xor_sync(0xffffffffu, a0, 1));
    a0 = fmaxf(a0, __shfl_xor_sync(0xffffffffu, a0, 2));
    a1 = fmaxf(a1, __shfl_xor_sync(0xffffffffu, a1, 1));
    a1 = fmaxf(a1, __shfl_xor_sync(0xffffffffu, a1, 2));
    const float d0 = a0 > 0.f ? a0 * (1.f / 32639.f) : 1.f;
    const float d1 = a1 > 0.f ? a1 * (1.f / 32639.f) : 1.f;
    const float i0 = 1.f / d0, i1 = 1.f / d1;
    if (q == 0) {
        Osc[(size_t)grow0 * 4 + head] = d0;
        Osc[(size_t)grow1 * 4 + head] = d1;
    }
#pragma unroll
    for (int j = 0; j < 16; j++) {
        const int c = coloff + j * 8 + 2 * q;
        int h0, l0, h1, l1;
        q2limb(acc2[j][0], i0, h0, l0); q2limb(acc2[j][1], i0, h1, l1);
        *(uint16_t*)(Oqh + (size_t)grow0 * Ee + c) = (uint16_t)((h0 & 255) | ((h1 & 255) << 8));
        *(uint16_t*)(Oql + (size_t)grow0 * Ee + c) = (uint16_t)((l0 & 255) | ((l1 & 255) << 8));
        q2limb(acc2[j][2], i1, h0, l0); q2limb(acc2[j][3], i1, h1, l1);
        *(uint16_t*)(Oqh + (size_t)grow1 * Ee + c) = (uint16_t)((h0 & 255) | ((h1 & 255) << 8));
        *(uint16_t*)(Oql + (size_t)grow1 * Ee + c) = (uint16_t)((l0 & 255) | ((l1 & 255) << 8));
    }
}

// ---------------------------------------------------------------------------
// launch
// ---------------------------------------------------------------------------
extern "C" void kernel_launch(void* const* d_in, const int* in_sizes, int n_in,
                              void* d_out, int out_size) {
    (void)in_sizes; (void)n_in; (void)out_size;
    const float* x  = (const float*)d_in[0];
    const float* wq = (const float*)d_in[1];
    const float* bq = (const float*)d_in[2];
    const float* wk = (const float*)d_in[3];
    const float* bk = (const float*)d_in[4];
    const float* wv = (const float*)d_in[5];
    const float* bv = (const float*)d_in[6];
    const float* wo = (const float*)d_in[7];
    const float* bo = (const float*)d_in[8];
    const float* w1 = (const float*)d_in[9];
    const float* b1 = (const float*)d_in[10];
    const float* w2 = (const float*)d_in[11];
    const float* b2 = (const float*)d_in[12];
    float* out = (float*)d_out;

    int8_t *xqh, *xql, *atqh, *atql, *x1qh, *x1ql, *hqh, *hql;
    int8_t *wqkvqh, *wqkvql, *woqh, *woql, *w1qh, *w1ql, *w2qh, *w2ql;
    uint16_t *qh, *ql;
    float *sx, *sat, *sx1, *sh, *swqkv, *swo, *sw1, *sw2, *x1f, *bqkv;
    cudaGetSymbolAddress((void**)&xqh, g_xqh);     cudaGetSymbolAddress((void**)&xql, g_xql);
    cudaGetSymbolAddress((void**)&sx, g_sx);
    cudaGetSymbolAddress((void**)&qh, g_qh);       cudaGetSymbolAddress((void**)&ql, g_ql);
    cudaGetSymbolAddress((void**)&atqh, g_atqh);   cudaGetSymbolAddress((void**)&atql, g_atql);
    cudaGetSymbolAddress((void**)&sat, g_sat);
    cudaGetSymbolAddress((void**)&x1f, g_x1f);
    cudaGetSymbolAddress((void**)&x1qh, g_x1qh);   cudaGetSymbolAddress((void**)&x1ql, g_x1ql);
    cudaGetSymbolAddress((void**)&sx1, g_sx1);
    cudaGetSymbolAddress((void**)&hqh, g_hqh);     cudaGetSymbolAddress((void**)&hql, g_hql);
    cudaGetSymbolAddress((void**)&sh, g_sh);
    cudaGetSymbolAddress((void**)&wqkvqh, g_wqkvqh); cudaGetSymbolAddress((void**)&wqkvql, g_wqkvql);
    cudaGetSymbolAddress((void**)&swqkv, g_swqkv);
    cudaGetSymbolAddress((void**)&woqh, g_woqh);   cudaGetSymbolAddress((void**)&woql, g_woql);
    cudaGetSymbolAddress((void**)&swo, g_swo);
    cudaGetSymbolAddress((void**)&w1qh, g_w1qh);   cudaGetSymbolAddress((void**)&w1ql, g_w1ql);
    cudaGetSymbolAddress((void**)&sw1, g_sw1);
    cudaGetSymbolAddress((void**)&w2qh, g_w2qh);   cudaGetSymbolAddress((void**)&w2ql, g_w2ql);
    cudaGetSymbolAddress((void**)&sw2, g_sw2);
    cudaGetSymbolAddress((void**)&bqkv, g_bqkv);

    cudaFuncSetAttribute(gemm_i8<0>, cudaFuncAttributeMaxDynamicSharedMemorySize, SMEM_I8);
    cudaFuncSetAttribute(gemm_i8<2>, cudaFuncAttributeMaxDynamicSharedMemorySize, SMEM_I8);
    cudaFuncSetAttribute(gemm_i8_blk, cudaFuncAttributeMaxDynamicSharedMemorySize, SMEM_I8);
    cudaFuncSetAttribute(attn_kernel, cudaFuncAttributeMaxDynamicSharedMemorySize, SMEM_ATTN);

    // 0: prep (bias + weight quant)
    prep_all<<<150, 256>>>(bq, bk, bv, wq, wk, wv, wo, w1, w2);
    // 1: quantize x rows (row scale)
    quant_rows<Ee><<<MM / 8, 256>>>(x, xqh, xql, sx);
    // 2: fused QKV (int8) -> bf16 planes
    gemm_i8<2><<<dim3(12, 384), 256, SMEM_I8>>>(xqh, xql, wqkvqh, wqkvql, sx, swqkv,
                                                bqkv, qh, ql, nullptr, nullptr, nullptr,
                                                NQKV, Ee);
    // 3: attention -> int8 limbs + per-(row,head) scales
    attn_kernel<<<Bb * 4, 256, SMEM_ATTN>>>(qh, ql, atqh, atql, sat);
    // 4: x1 = x + attn @ wo + bo (block-scaled A, nblk=4) -> f32
    gemm_i8_blk<<<dim3(4, 384), 512, SMEM_I8>>>(atqh, atql, woqh, woql, sat, swo,
                                                bo, x, x1f, Ee, Ee);
    // 5: quantize x1 rows (row scale)
    quant_rows<Ee><<<MM / 8, 256>>>(x1f, x1qh, x1ql, sx1);
    // 6: h = relu(x1 @ w1 + b1) -> int8 limbs + per-(row,128-block) scales
    gemm_i8<0><<<dim3(16, 384), 256, SMEM_I8>>>(x1qh, x1ql, w1qh, w1ql, sx1, sw1,
                                                b1, nullptr, nullptr, hqh, hql, sh,
                                                Ff, Ee);
    // 7: out = x1 + h @ w2 + b2 (block-scaled A, nblk=16) -> f32
    gemm_i8_blk<<<dim3(4, 384), 512, SMEM_I8>>>(hqh, hql, w2qh, w2ql, sh, sw2,
                                                b2, x1f, out, Ee, Ff);
}

// round 13
// speedup vs baseline: 1.0296x; 1.0296x over previous
#include <cuda_runtime.h>
#include <cstdint>

// ---------------------------------------------------------------------------
// Transformer block — all GEMMs int8 2-limb IMMA (q = 256h + l, 15-bit, exact
// s32 accum of HH and HL+LH, per-row/per-col scales). Attention bf16x3 HMMA.
// R13 = R11 structure + bf16-plane intermediates for h and attn (traffic cut).
// B=384, S=128, E=512, H=4, D=128, F=2048.
// ---------------------------------------------------------------------------

constexpr int Bb = 384, Ss = 128, Ee = 512, Ff = 2048;
constexpr int MM = Bb * Ss, NQKV = 3 * Ee;

// activations
__device__ int8_t   g_xqh [(size_t)MM * Ee],  g_xql [(size_t)MM * Ee];
__device__ float    g_sx[MM];
__device__ uint16_t g_qh [(size_t)MM * NQKV], g_ql [(size_t)MM * NQKV];
__device__ uint16_t g_ath[(size_t)MM * Ee],   g_atl[(size_t)MM * Ee];
__device__ int8_t   g_atqh[(size_t)MM * Ee],  g_atql[(size_t)MM * Ee];
__device__ float    g_sat[MM];
__device__ float    g_x1f[(size_t)MM * Ee];
__device__ int8_t   g_x1qh[(size_t)MM * Ee],  g_x1ql[(size_t)MM * Ee];
__device__ float    g_sx1[MM];
__device__ uint16_t g_hph[(size_t)MM * Ff],   g_hpl[(size_t)MM * Ff];
__device__ int8_t   g_hqh [(size_t)MM * Ff],  g_hql [(size_t)MM * Ff];
__device__ float    g_sh[MM];
// weights (int8 limbs, [N][K], per-col scale)
__device__ int8_t   g_wqkvqh[(size_t)NQKV * Ee], g_wqkvql[(size_t)NQKV * Ee];
__device__ float    g_swqkv[NQKV];
__device__ int8_t   g_woqh[(size_t)Ee * Ee],  g_woql[(size_t)Ee * Ee];
__device__ float    g_swo[Ee];
__device__ int8_t   g_w1qh[(size_t)Ff * Ee],  g_w1ql[(size_t)Ff * Ee];
__device__ float    g_sw1[Ff];
__device__ int8_t   g_w2qh[(size_t)Ee * Ff],  g_w2ql[(size_t)Ee * Ff];
__device__ float    g_sw2[Ee];
__device__ float    g_bqkv[NQKV];

__device__ __forceinline__ void split2(float v, uint16_t& h, uint16_t& l) {
    float hf;
    asm("cvt.rn.bf16.f32 %0, %1;" : "=h"(h) : "f"(v));
    asm("cvt.f32.bf16 %0, %1;"    : "=f"(hf) : "h"(h));
    asm("cvt.rn.bf16.f32 %0, %1;" : "=h"(l) : "f"(v - hf));
}
__device__ __forceinline__ uint32_t cvta_s(const void* p) {
    uint32_t a;
    asm("{\n\t.reg .u64 t;\n\tcvta.to.shared.u64 t, %1;\n\tcvt.u32.u64 %0, t;\n\t}"
        : "=r"(a) : "l"(p));
    return a;
}
#define CP16(s, g)  asm volatile("cp.async.cg.shared.global [%0], [%1], 16;" ::"r"(s), "l"(g))
#define CPCOMMIT()  asm volatile("cp.async.commit_group;" ::: "memory")
__device__ __forceinline__ void cpwait(int n) {
    if (n >= 2)      asm volatile("cp.async.wait_group 2;" ::: "memory");
    else if (n == 1) asm volatile("cp.async.wait_group 1;" ::: "memory");
    else             asm volatile("cp.async.wait_group 0;" ::: "memory");
}
#define LDSM4(r0, r1, r2, r3, a) \
    asm volatile("ldmatrix.sync.aligned.m8n8.x4.shared.b16 {%0,%1,%2,%3}, [%4];" \
        : "=r"(r0), "=r"(r1), "=r"(r2), "=r"(r3) : "r"(a))
#define LDSM4T(r0, r1, r2, r3, a) \
    asm volatile("ldmatrix.sync.aligned.m8n8.x4.trans.shared.b16 {%0,%1,%2,%3}, [%4];" \
        : "=r"(r0), "=r"(r1), "=r"(r2), "=r"(r3) : "r"(a))
#define STS32(a, v) asm volatile("st.shared.b32 [%0], %1;" ::"r"(a), "r"(v) : "memory")

__device__ __forceinline__ void mma16(float* d, const uint32_t* a,
                                      uint32_t b0, uint32_t b1) {
    asm("mma.sync.aligned.m16n8k16.row.col.f32.bf16.bf16.f32 "
        "{%0,%1,%2,%3}, {%4,%5,%6,%7}, {%8,%9}, {%0,%1,%2,%3};\n"
        : "+f"(d[0]), "+f"(d[1]), "+f"(d[2]), "+f"(d[3])
        : "r"(a[0]), "r"(a[1]), "r"(a[2]), "r"(a[3]), "r"(b0), "r"(b1));
}
__device__ __forceinline__ void mma3(float* d, const uint32_t* ah, const uint32_t* al,
                                     uint32_t bh0, uint32_t bh1,
                                     uint32_t bl0, uint32_t bl1) {
    mma16(d, ah, bh0, bh1);
    mma16(d, al, bh0, bh1);
    mma16(d, ah, bl0, bl1);
}
__device__ __forceinline__ void imma32(int* d, const uint32_t* a,
                                       uint32_t b0, uint32_t b1) {
    asm("mma.sync.aligned.m16n8k32.row.col.s32.s8.s8.s32 "
        "{%0,%1,%2,%3}, {%4,%5,%6,%7}, {%8,%9}, {%0,%1,%2,%3};\n"
        : "+r"(d[0]), "+r"(d[1]), "+r"(d[2]), "+r"(d[3])
        : "r"(a[0]), "r"(a[1]), "r"(a[2]), "r"(a[3]), "r"(b0), "r"(b1));
}
__device__ __forceinline__ void q2limb(float v, float inv, int& h, int& l) {
    const int q = (int)rintf(v * inv);
    h = (q + 128) >> 8;
    l = q - (h << 8);
}
__device__ __forceinline__ float b2f_lo(uint32_t u) {
    return __uint_as_float(u << 16);
}
__device__ __forceinline__ float b2f_hi(uint32_t u) {
    return __uint_as_float(u & 0xFFFF0000u);
}

// ---------------------------------------------------------------------------
// prep: bias concat + int8 quant of all weights (per-out-col scale, [N][K])
// ---------------------------------------------------------------------------
__global__ void prep_all(const float* __restrict__ bq, const float* __restrict__ bk,
                         const float* __restrict__ bv,
                         const float* __restrict__ wq, const float* __restrict__ wk,
                         const float* __restrict__ wv, const float* __restrict__ wo,
                         const float* __restrict__ w1, const float* __restrict__ w2) {
    __shared__ uint32_t tile[32][33];
    __shared__ float smax[8][32];
    const int bidx = blockIdx.x;
    const int lx = threadIdx.x & 31, ly = threadIdx.x >> 5;
    if (bidx < 6) {
        const int i = bidx * 256 + threadIdx.x;
        if (i < NQKV)
            g_bqkv[i] = i < 512 ? bq[i] : (i < 1024 ? bk[i - 512] : bv[i - 1024]);
        return;
    }
    const int id = bidx - 6;
    const float* W; int8_t *Qh, *Ql; float* Sd;
    int Nsrc, K, nb, srccol, destrow;
    if (id < 48) {
        nb = id * 32;
        W = nb < 512 ? wq : (nb < 1024 ? wk : wv);
        srccol = nb & 511; destrow = nb;
        Qh = g_wqkvqh; Ql = g_wqkvql; Sd = g_swqkv; Nsrc = 512; K = 512;
    } else if (id < 64) {
        nb = (id - 48) * 32; srccol = nb; destrow = nb;
        W = wo; Qh = g_woqh; Ql = g_woql; Sd = g_swo; Nsrc = 512; K = 512;
    } else if (id < 128) {
        nb = (id - 64) * 32; srccol = nb; destrow = nb;
        W = w1; Qh = g_w1qh; Ql = g_w1ql; Sd = g_sw1; Nsrc = 2048; K = 512;
    } else {
        nb = (id - 128) * 32; srccol = nb; destrow = nb;
        W = w2; Qh = g_w2qh; Ql = g_w2ql; Sd = g_sw2; Nsrc = 512; K = 2048;
    }
    float mx = 0.f;
    for (int k = ly; k < K; k += 8)
        mx = fmaxf(mx, fabsf(W[(size_t)k * Nsrc + srccol + lx]));
    smax[ly][lx] = mx;
    __syncthreads();
    if (ly == 0) {
        for (int i = 1; i < 8; i++) mx = fmaxf(mx, smax[i][lx]);
        const float d = mx > 0.f ? mx * (1.f / 32639.f) : 1.f;
        smax[0][lx] = 1.f / d;
        Sd[destrow + lx] = d;
    }
    __syncthreads();
    const float inv = smax[0][lx];
    for (int kb = 0; kb < K; kb += 32) {
        for (int j = ly; j < 32; j += 8) {
            int h, l;
            q2limb(W[(size_t)(kb + j) * Nsrc + srccol + lx], inv, h, l);
            tile[j][lx] = (uint32_t)(uint8_t)h | ((uint32_t)(uint8_t)l << 8);
        }
        __syncthreads();
        for (int j = ly; j < 32; j += 8) {
            const uint32_t t = tile[lx][j];
            const size_t o = (size_t)(destrow + j) * K + kb + lx;
            Qh[o] = (int8_t)(t & 255);
            Ql[o] = (int8_t)((t >> 8) & 255);
        }
        __syncthreads();
    }
}

// quant_rows: f32 source, per-row scale
template <int KQ>
__global__ __launch_bounds__(256)
void quant_rows(const float* __restrict__ src, int8_t* __restrict__ qh,
                int8_t* __restrict__ ql, float* __restrict__ sc) {
    const int w = threadIdx.x >> 5, lane = threadIdx.x & 31;
    const int row = blockIdx.x * 8 + w;
    const float* s = src + (size_t)row * KQ;
    constexpr int J = KQ / 128;
    float4 v[J];
    float mx = 0.f;
#pragma unroll
    for (int j = 0; j < J; j++) {
        v[j] = *(const float4*)(s + j * 128 + lane * 4);
        mx = fmaxf(mx, fmaxf(fmaxf(fabsf(v[j].x), fabsf(v[j].y)),
                             fmaxf(fabsf(v[j].z), fabsf(v[j].w))));
    }
#pragma unroll
    for (int o = 16; o; o >>= 1) mx = fmaxf(mx, __shfl_xor_sync(0xffffffffu, mx, o));
    const float d = mx > 0.f ? mx * (1.f / 32639.f) : 1.f;
    const float inv = 1.f / d;
    if (lane == 0) sc[row] = d;
#pragma unroll
    for (int j = 0; j < J; j++) {
        int h0, l0, h1, l1, h2, l2, h3, l3;
        q2limb(v[j].x, inv, h0, l0); q2limb(v[j].y, inv, h1, l1);
        q2limb(v[j].z, inv, h2, l2); q2limb(v[j].w, inv, h3, l3);
        *(uint32_t*)(qh + (size_t)row * KQ + j * 128 + lane * 4) =
            (h0 & 255) | ((h1 & 255) << 8) | ((h2 & 255) << 16) | ((h3 & 255) << 24);
        *(uint32_t*)(ql + (size_t)row * KQ + j * 128 + lane * 4) =
            (l0 & 255) | ((l1 & 255) << 8) | ((l2 & 255) << 16) | ((l3 & 255) << 24);
    }
}

// quant_rows_p: bf16 hi/lo plane source (v = hi + lo), per-row scale
template <int KQ>
__global__ __launch_bounds__(256)
void quant_rows_p(const uint16_t* __restrict__ ph, const uint16_t* __restrict__ pl,
                  int8_t* __restrict__ qh, int8_t* __restrict__ ql,
                  float* __restrict__ sc) {
    const int w = threadIdx.x >> 5, lane = threadIdx.x & 31;
    const int row = blockIdx.x * 8 + w;
    constexpr int J = KQ / 128;
    float v[J][4];
    float mx = 0.f;
#pragma unroll
    for (int j = 0; j < J; j++) {
        const uint2 uh = *(const uint2*)(ph + (size_t)row * KQ + j * 128 + lane * 4);
        const uint2 ul = *(const uint2*)(pl + (size_t)row * KQ + j * 128 + lane * 4);
        v[j][0] = b2f_lo(uh.x) + b2f_lo(ul.x);
        v[j][1] = b2f_hi(uh.x) + b2f_hi(ul.x);
        v[j][2] = b2f_lo(uh.y) + b2f_lo(ul.y);
        v[j][3] = b2f_hi(uh.y) + b2f_hi(ul.y);
        mx = fmaxf(mx, fmaxf(fmaxf(fabsf(v[j][0]), fabsf(v[j][1])),
                             fmaxf(fabsf(v[j][2]), fabsf(v[j][3]))));
    }
#pragma unroll
    for (int o = 16; o; o >>= 1) mx = fmaxf(mx, __shfl_xor_sync(0xffffffffu, mx, o));
    const float d = mx > 0.f ? mx * (1.f / 32639.f) : 1.f;
    const float inv = 1.f / d;
    if (lane == 0) sc[row] = d;
#pragma unroll
    for (int j = 0; j < J; j++) {
        int h0, l0, h1, l1, h2, l2, h3, l3;
        q2limb(v[j][0], inv, h0, l0); q2limb(v[j][1], inv, h1, l1);
        q2limb(v[j][2], inv, h2, l2); q2limb(v[j][3], inv, h3, l3);
        *(uint32_t*)(qh + (size_t)row * KQ + j * 128 + lane * 4) =
            (h0 & 255) | ((h1 & 255) << 8) | ((h2 & 255) << 16) | ((h3 & 255) << 24);
        *(uint32_t*)(ql + (size_t)row * KQ + j * 128 + lane * 4) =
            (l0 & 255) | ((l1 & 255) << 8) | ((l2 & 255) << 16) | ((l3 & 255) << 24);
    }
}

// ---------------------------------------------------------------------------
// int8 2-limb GEMM: v = (A@B^T)*sa*sb + bias. Tile 128x128, BK=128, 3-stage,
// 8 warps 2x4 (warp 64x32).
// EPI: 0 relu->f32; 1 +res->f32; 2 ->bf16 planes; 3 relu->bf16 planes.
// ---------------------------------------------------------------------------
constexpr int I8_STGB = 65536;
constexpr int SMEM_I8 = 3 * I8_STGB;

template <int EPI>
__global__ __launch_bounds__(256, 1)
void gemm_i8(const int8_t* __restrict__ Ah_, const int8_t* __restrict__ Al_,
             const int8_t* __restrict__ Bh_, const int8_t* __restrict__ Bl_,
             const float* __restrict__ sa, const float* __restrict__ sb,
             const float* __restrict__ bias, const float* __restrict__ res,
             float* __restrict__ out,
             uint16_t* __restrict__ Ch, uint16_t* __restrict__ Cl,
             int Nout, int K) {
    extern __shared__ char smraw[];
    const uint32_t sbase = cvta_s(smraw);
    const int tid = threadIdx.x, wid = tid >> 5, lane = tid & 31;
    const int wm = wid >> 2, wn = wid & 3;
    const int mB = blockIdx.y * 128, nB = blockIdx.x * 128;
    const int l7 = lane & 7, l8 = (lane >> 3) & 1, l16 = lane >> 4;

    const int trow = tid >> 3, tch = tid & 7;
    const uint32_t dst0 = trow * 128 + (((uint32_t)tch ^ (trow & 7)) << 4);
    const int8_t* bp[4];
    bp[0] = Ah_ + (size_t)(mB + trow) * K + tch * 16;
    bp[1] = Al_ + (size_t)(mB + trow) * K + tch * 16;
    bp[2] = Bh_ + (size_t)(nB + trow) * K + tch * 16;
    bp[3] = Bl_ + (size_t)(nB + trow) * K + tch * 16;

    int hh[4][4][4], cr[4][4][4];
#pragma unroll
    for (int a = 0; a < 4; a++)
#pragma unroll
        for (int b = 0; b < 4; b++)
#pragma unroll
            for (int c = 0; c < 4; c++) { hh[a][b][c] = 0; cr[a][b][c] = 0; }

    auto issue = [&](int s) {
        const uint32_t stb = sbase + (s % 3) * I8_STGB;
        const int kg = s * 128;
#pragma unroll
        for (int pl = 0; pl < 4; pl++) {
            const int8_t* gp = bp[pl] + kg;
#pragma unroll
            for (int i2 = 0; i2 < 4; i2++)
                CP16(stb + pl * 16384 + dst0 + i2 * 4096, gp + (size_t)i2 * 32 * K);
        }
        CPCOMMIT();
    };

    const int nT = K >> 7;
    issue(0);
    if (nT > 1) issue(1);

    const uint32_t raBase[4] = {
        (uint32_t)(wm * 64 + 0 + l8 * 8 + l7),  (uint32_t)(wm * 64 + 16 + l8 * 8 + l7),
        (uint32_t)(wm * 64 + 32 + l8 * 8 + l7), (uint32_t)(wm * 64 + 48 + l8 * 8 + l7)};
    const uint32_t rbBase[2] = {
        (uint32_t)(wn * 32 + l8 * 8 + l7), (uint32_t)(wn * 32 + 16 + l8 * 8 + l7)};

    for (int t = 0; t < nT; t++) {
        cpwait(t < nT - 1 ? 1 : 0);
        __syncthreads();
        if (t + 2 < nT) issue(t + 2);
        const uint32_t stb = sbase + (t % 3) * I8_STGB;
#pragma unroll
        for (int b = 0; b < 4; b++) {
            uint32_t ahf[4][4], alf[4][4];
#pragma unroll
            for (int mi = 0; mi < 4; mi++) {
                const uint32_t r = raBase[mi];
                const uint32_t base = stb + r * 128;
                const uint32_t ch = (uint32_t)((2 * b + l16) ^ (r & 7)) << 4;
                LDSM4(ahf[mi][0], ahf[mi][1], ahf[mi][2], ahf[mi][3], base + ch);
                LDSM4(alf[mi][0], alf[mi][1], alf[mi][2], alf[mi][3], base + 16384 + ch);
            }
#pragma unroll
            for (int j2 = 0; j2 < 2; j2++) {
                const uint32_t r = rbBase[j2];
                const uint32_t baseB = stb + 32768 + r * 128;
                const uint32_t ch = (uint32_t)((2 * b + l16) ^ (r & 7)) << 4;
                uint32_t bh0, bh1, bh2, bh3, bl0, bl1, bl2, bl3;
                LDSM4(bh0, bh1, bh2, bh3, baseB + ch);
                LDSM4(bl0, bl1, bl2, bl3, baseB + 16384 + ch);
#pragma unroll
                for (int mi = 0; mi < 4; mi++) {
                    imma32(hh[mi][2 * j2],     ahf[mi], bh0, bh2);
                    imma32(hh[mi][2 * j2 + 1], ahf[mi], bh1, bh3);
                }
#pragma unroll
                for (int mi = 0; mi < 4; mi++) {
                    imma32(cr[mi][2 * j2],     ahf[mi], bl0, bl2);
                    imma32(cr[mi][2 * j2 + 1], ahf[mi], bl1, bl3);
                }
#pragma unroll
                for (int mi = 0; mi < 4; mi++) {
                    imma32(cr[mi][2 * j2],     alf[mi], bh0, bh2);
                    imma32(cr[mi][2 * j2 + 1], alf[mi], bh1, bh3);
                }
            }
        }
    }

#pragma unroll
    for (int mi = 0; mi < 4; mi++) {
        const int r0 = mB + wm * 64 + mi * 16 + (lane >> 2);
        const int r1 = r0 + 8;
        const float sa0 = sa[r0], sa1 = sa[r1];
#pragma unroll
        for (int nj = 0; nj < 4; nj++) {
            const int c = nB + wn * 32 + nj * 8 + 2 * (lane & 3);
            const float sb0 = sb[c], sb1 = sb[c + 1];
            const float b0 = bias[c], b1v = bias[c + 1];
            float v0 = ((float)hh[mi][nj][0] * 65536.f + (float)cr[mi][nj][0] * 256.f) * (sa0 * sb0) + b0;
            float v1 = ((float)hh[mi][nj][1] * 65536.f + (float)cr[mi][nj][1] * 256.f) * (sa0 * sb1) + b1v;
            float v2 = ((float)hh[mi][nj][2] * 65536.f + (float)cr[mi][nj][2] * 256.f) * (sa1 * sb0) + b0;
            float v3 = ((float)hh[mi][nj][3] * 65536.f + (float)cr[mi][nj][3] * 256.f) * (sa1 * sb1) + b1v;
            if (EPI == 0 || EPI == 3) {
                v0 = fmaxf(v0, 0.f); v1 = fmaxf(v1, 0.f);
                v2 = fmaxf(v2, 0.f); v3 = fmaxf(v3, 0.f);
            }
            if (EPI == 1) {
                const float2 rv0 = *(const float2*)(res + (size_t)r0 * Nout + c);
                const float2 rv1 = *(const float2*)(res + (size_t)r1 * Nout + c);
                v0 += rv0.x; v1 += rv0.y; v2 += rv1.x; v3 += rv1.y;
            }
            if (EPI == 2 || EPI == 3) {
                uint16_t h0, l0, h1, l1;
                split2(v0, h0, l0); split2(v1, h1, l1);
                *(uint32_t*)(Ch + (size_t)r0 * Nout + c) = (uint32_t)h0 | ((uint32_t)h1 << 16);
                *(uint32_t*)(Cl + (size_t)r0 * Nout + c) = (uint32_t)l0 | ((uint32_t)l1 << 16);
                split2(v2, h0, l0); split2(v3, h1, l1);
                *(uint32_t*)(Ch + (size_t)r1 * Nout + c) = (uint32_t)h0 | ((uint32_t)h1 << 16);
                *(uint32_t*)(Cl + (size_t)r1 * Nout + c) = (uint32_t)l0 | ((uint32_t)l1 << 16);
            } else {
                *(float2*)(out + (size_t)r0 * Nout + c) = make_float2(v0, v1);
                *(float2*)(out + (size_t)r1 * Nout + c) = make_float2(v2, v3);
            }
        }
    }
}

// ---------------------------------------------------------------------------
// Attention on bf16 planes (R8/R10 form) — writes bf16 planes.
// ---------------------------------------------------------------------------
constexpr int SMEM_ATTN = 6 * 32768;

__global__ __launch_bounds__(256, 1)
void attn_kernel(const uint16_t* __restrict__ qh, const uint16_t* __restrict__ ql,
                 uint16_t* __restrict__ Oh, uint16_t* __restrict__ Ol) {
    extern __shared__ char smraw[];
    const uint32_t sb = cvta_s(smraw);
    const uint32_t QH = sb, QL = sb + 32768, KH = sb + 65536, KL = sb + 98304;
    const uint32_t VH = sb + 131072, VL = sb + 163840;

    const int tid = threadIdx.x, bh = blockIdx.x;
    const int bb = bh >> 2, head = bh & 3;
    const size_t rowbase = (size_t)bb * Ss * NQKV;
    const int coloff = head * 128;
    const size_t obase = (size_t)bb * Ss * Ee + (size_t)coloff;

#pragma unroll
    for (int i = 0; i < 48; i++) {
        const int idx = tid + i * 256;
        const int p = idx >> 11, rem = idx & 2047;
        const int row = rem >> 4, c = rem & 15;
        const uint16_t* base = (p & 1) ? ql : qh;
        const size_t src = rowbase + (size_t)row * NQKV + (p >> 1) * 512 + coloff + c * 8;
        CP16(sb + p * 32768 + row * 256 + ((uint32_t)(c ^ (row & 7)) << 4), base + src);
    }
    CPCOMMIT();
    cpwait(0);
    __syncthreads();

    const int wid = tid >> 5, lane = tid & 31;
    const int g = lane >> 2, q = lane & 3;
    const int l7 = lane & 7, l8 = (lane >> 3) & 1, l16 = lane >> 4;
    const int rbase = wid * 16;
    const int ra = rbase + l8 * 8 + l7;

    float acc[16][4];
#pragma unroll
    for (int j = 0; j < 16; j++)
#pragma unroll
        for (int c = 0; c < 4; c++) acc[j][c] = 0.f;

#pragma unroll
    for (int kk = 0; kk < 8; kk++) {
        const uint32_t ca = ((uint32_t)((2 * kk + l16) ^ (ra & 7)) << 4) + ra * 256;
        uint32_t ah[4], al[4];
        LDSM4(ah[0], ah[1], ah[2], ah[3], QH + ca);
        LDSM4(al[0], al[1], al[2], al[3], QL + ca);
#pragma unroll
        for (int j2 = 0; j2 < 8; j2++) {
            const int rb = j2 * 16 + l8 * 8 + l7;
            const uint32_t cb = ((uint32_t)((2 * kk + l16) ^ (rb & 7)) << 4) + rb * 256;
            uint32_t bh_[4], bl_[4];
            LDSM4(bh_[0], bh_[1], bh_[2], bh_[3], KH + cb);
            LDSM4(bl_[0], bl_[1], bl_[2], bl_[3], KL + cb);
            mma3(acc[j2 * 2],     ah, al, bh_[0], bh_[2], bl_[0], bl_[2]);
            mma3(acc[j2 * 2 + 1], ah, al, bh_[1], bh_[3], bl_[1], bl_[3]);
        }
    }

    float m0 = -1e30f, m1 = -1e30f;
#pragma unroll
    for (int j = 0; j < 16; j++) {
        m0 = fmaxf(m0, fmaxf(acc[j][0], acc[j][1]));
        m1 = fmaxf(m1, fmaxf(acc[j][2], acc[j][3]));
    }
    m0 = fmaxf(m0, __shfl_xor_sync(0xffffffffu, m0, 1));
    m0 = fmaxf(m0, __shfl_xor_sync(0xffffffffu, m0, 2));
    m1 = fmaxf(m1, __shfl_xor_sync(0xffffffffu, m1, 1));
    m1 = fmaxf(m1, __shfl_xor_sync(0xffffffffu, m1, 2));
    float s0 = 0.f, s1 = 0.f;
#pragma unroll
    for (int j = 0; j < 16; j++) {
        acc[j][0] = expf(acc[j][0] - m0);
        acc[j][1] = expf(acc[j][1] - m0);
        acc[j][2] = expf(acc[j][2] - m1);
        acc[j][3] = expf(acc[j][3] - m1);
        s0 += acc[j][0] + acc[j][1];
        s1 += acc[j][2] + acc[j][3];
    }
    s0 += __shfl_xor_sync(0xffffffffu, s0, 1);
    s0 += __shfl_xor_sync(0xffffffffu, s0, 2);
    s1 += __shfl_xor_sync(0xffffffffu, s1, 1);
    s1 += __shfl_xor_sync(0xffffffffu, s1, 2);
    const float r0s = 1.f / s0, r1s = 1.f / s1;

    const int pr0 = rbase + g, pr1 = pr0 + 8;
#pragma unroll
    for (int j = 0; j < 16; j++) {
        const uint32_t off0 = pr0 * 256 + ((uint32_t)(j ^ (pr0 & 7)) << 4) + 4 * q;
        const uint32_t off1 = pr1 * 256 + ((uint32_t)(j ^ (pr1 & 7)) << 4) + 4 * q;
        uint16_t h0, l0, h1, l1;
        split2(acc[j][0] * r0s, h0, l0); split2(acc[j][1] * r0s, h1, l1);
        STS32(QH + off0, (uint32_t)h0 | ((uint32_t)h1 << 16));
        STS32(QL + off0, (uint32_t)l0 | ((uint32_t)l1 << 16));
        split2(acc[j][2] * r1s, h0, l0); split2(acc[j][3] * r1s, h1, l1);
        STS32(QH + off1, (uint32_t)h0 | ((uint32_t)h1 << 16));
        STS32(QL + off1, (uint32_t)l0 | ((uint32_t)l1 << 16));
    }
    __syncwarp();

    float acc2[16][4];
#pragma unroll
    for (int j = 0; j < 16; j++)
#pragma unroll
        for (int c = 0; c < 4; c++) acc2[j][c] = 0.f;

#pragma unroll
    for (int kk = 0; kk < 8; kk++) {
        const uint32_t ca = ((uint32_t)((2 * kk + l16) ^ (ra & 7)) << 4) + ra * 256;
        uint32_t ah[4], al[4];
        LDSM4(ah[0], ah[1], ah[2], ah[3], QH + ca);
        LDSM4(al[0], al[1], al[2], al[3], QL + ca);
        const int krow = kk * 16 + l8 * 8 + l7;
#pragma unroll
        for (int j2 = 0; j2 < 8; j2++) {
            const int cj = j2 * 2 + l16;
            const uint32_t cb = ((uint32_t)(cj ^ (krow & 7)) << 4) + krow * 256;
            uint32_t vh_[4], vl_[4];
            LDSM4T(vh_[0], vh_[1], vh_[2], vh_[3], VH + cb);
            LDSM4T(vl_[0], vl_[1], vl_[2], vl_[3], VL + cb);
            mma3(acc2[j2 * 2],     ah, al, vh_[0], vh_[1], vl_[0], vl_[1]);
            mma3(acc2[j2 * 2 + 1], ah, al, vh_[2], vh_[3], vl_[2], vl_[3]);
        }
    }

#pragma unroll
    for (int j = 0; j < 16; j++) {
        const int c = j * 8 + 2 * q;
        const size_t o0 = obase + (size_t)(rbase + g) * Ee + c;
        const size_t o1 = o0 + (size_t)8 * Ee;
        uint16_t h0, l0, h1, l1;
        split2(acc2[j][0], h0, l0); split2(acc2[j][1], h1, l1);
        *(uint32_t*)(Oh + o0) = (uint32_t)h0 | ((uint32_t)h1 << 16);
        *(uint32_t*)(Ol + o0) = (uint32_t)l0 | ((uint32_t)l1 << 16);
        split2(acc2[j][2], h0, l0); split2(acc2[j][3], h1, l1);
        *(uint32_t*)(Oh + o1) = (uint32_t)h0 | ((uint32_t)h1 << 16);
        *(uint32_t*)(Ol + o1) = (uint32_t)l0 | ((uint32_t)l1 << 16);
    }
}

// ---------------------------------------------------------------------------
// launch
// ---------------------------------------------------------------------------
extern "C" void kernel_launch(void* const* d_in, const int* in_sizes, int n_in,
                              void* d_out, int out_size) {
    (void)in_sizes; (void)n_in; (void)out_size;
    const float* x  = (const float*)d_in[0];
    const float* wq = (const float*)d_in[1];
    const float* bq = (const float*)d_in[2];
    const float* wk = (const float*)d_in[3];
    const float* bk = (const float*)d_in[4];
    const float* wv = (const float*)d_in[5];
    const float* bv = (const float*)d_in[6];
    const float* wo = (const float*)d_in[7];
    const float* bo = (const float*)d_in[8];
    const float* w1 = (const float*)d_in[9];
    const float* b1 = (const float*)d_in[10];
    const float* w2 = (const float*)d_in[11];
    const float* b2 = (const float*)d_in[12];
    float* out = (float*)d_out;

    int8_t *xqh, *xql, *atqh, *atql, *x1qh, *x1ql, *hqh, *hql;
    int8_t *wqkvqh, *wqkvql, *woqh, *woql, *w1qh, *w1ql, *w2qh, *w2ql;
    uint16_t *qh, *ql, *ath, *atl, *hph, *hpl;
    float *sx, *sat, *sx1, *sh, *swqkv, *swo, *sw1, *sw2, *x1f, *bqkv;
    cudaGetSymbolAddress((void**)&xqh, g_xqh);     cudaGetSymbolAddress((void**)&xql, g_xql);
    cudaGetSymbolAddress((void**)&sx, g_sx);
    cudaGetSymbolAddress((void**)&qh, g_qh);       cudaGetSymbolAddress((void**)&ql, g_ql);
    cudaGetSymbolAddress((void**)&ath, g_ath);     cudaGetSymbolAddress((void**)&atl, g_atl);
    cudaGetSymbolAddress((void**)&atqh, g_atqh);   cudaGetSymbolAddress((void**)&atql, g_atql);
    cudaGetSymbolAddress((void**)&sat, g_sat);
    cudaGetSymbolAddress((void**)&x1f, g_x1f);
    cudaGetSymbolAddress((void**)&x1qh, g_x1qh);   cudaGetSymbolAddress((void**)&x1ql, g_x1ql);
    cudaGetSymbolAddress((void**)&sx1, g_sx1);
    cudaGetSymbolAddress((void**)&hph, g_hph);     cudaGetSymbolAddress((void**)&hpl, g_hpl);
    cudaGetSymbolAddress((void**)&hqh, g_hqh);     cudaGetSymbolAddress((void**)&hql, g_hql);
    cudaGetSymbolAddress((void**)&sh, g_sh);
    cudaGetSymbolAddress((void**)&wqkvqh, g_wqkvqh); cudaGetSymbolAddress((void**)&wqkvql, g_wqkvql);
    cudaGetSymbolAddress((void**)&swqkv, g_swqkv);
    cudaGetSymbolAddress((void**)&woqh, g_woqh);   cudaGetSymbolAddress((void**)&woql, g_woql);
    cudaGetSymbolAddress((void**)&swo, g_swo);
    cudaGetSymbolAddress((void**)&w1qh, g_w1qh);   cudaGetSymbolAddress((void**)&w1ql, g_w1ql);
    cudaGetSymbolAddress((void**)&sw1, g_sw1);
    cudaGetSymbolAddress((void**)&w2qh, g_w2qh);   cudaGetSymbolAddress((void**)&w2ql, g_w2ql);
    cudaGetSymbolAddress((void**)&sw2, g_sw2);
    cudaGetSymbolAddress((void**)&bqkv, g_bqkv);

    cudaFuncSetAttribute(gemm_i8<1>, cudaFuncAttributeMaxDynamicSharedMemorySize, SMEM_I8);
    cudaFuncSetAttribute(gemm_i8<2>, cudaFuncAttributeMaxDynamicSharedMemorySize, SMEM_I8);
    cudaFuncSetAttribute(gemm_i8<3>, cudaFuncAttributeMaxDynamicSharedMemorySize, SMEM_I8);
    cudaFuncSetAttribute(attn_kernel, cudaFuncAttributeMaxDynamicSharedMemorySize, SMEM_ATTN);

    // 0: prep (bias concat + int8 quant of all weights)
    prep_all<<<150, 256>>>(bq, bk, bv, wq, wk, wv, wo, w1, w2);
    // 1: quantize x rows (f32 source)
    quant_rows<Ee><<<MM / 8, 256>>>(x, xqh, xql, sx);
    // 2: fused QKV (int8) -> bf16 planes
    gemm_i8<2><<<dim3(12, 384), 256, SMEM_I8>>>(xqh, xql, wqkvqh, wqkvql, sx, swqkv,
                                                bqkv, nullptr, nullptr, qh, ql, NQKV, Ee);
    // 3: attention -> bf16 planes
    attn_kernel<<<Bb * 4, 256, SMEM_ATTN>>>(qh, ql, ath, atl);
    // 4: quantize attention rows (plane source)
    quant_rows_p<Ee><<<MM / 8, 256>>>(ath, atl, atqh, atql, sat);
    // 5: x1 = x + attn @ wo + bo (int8) -> f32
    gemm_i8<1><<<dim3(4, 384), 256, SMEM_I8>>>(atqh, atql, woqh, woql, sat, swo,
                                               bo, x, x1f, nullptr, nullptr, Ee, Ee);
    // 6: quantize x1 rows (f32 source)
    quant_rows<Ee><<<MM / 8, 256>>>(x1f, x1qh, x1ql, sx1);
    // 7: h = relu(x1 @ w1 + b1) (int8) -> bf16 planes
    gemm_i8<3><<<dim3(16, 384), 256, SMEM_I8>>>(x1qh, x1ql, w1qh, w1ql, sx1, sw1,
                                                b1, nullptr, nullptr, hph, hpl, Ff, Ee);
    // 8: quantize h rows (plane source)
    quant_rows_p<Ff><<<MM / 8, 256>>>(hph, hpl, hqh, hql, sh);
    // 9: out = x1 + h @ w2 + b2 (int8) -> f32
    gemm_i8<1><<<dim3(4, 384), 256, SMEM_I8>>>(hqh, hql, w2qh, w2ql, sh, sw2,
                                               b2, x1f, out, nullptr, nullptr, Ee, Ff);
}

// round 14
// speedup vs baseline: 1.0939x; 1.0624x over previous
#include <cuda_runtime.h>
#include <cstdint>

// ---------------------------------------------------------------------------
// Transformer block — all GEMMs int8 2-limb IMMA (q = 256h + l, 15-bit).
// R14 = R11 + int8 QK^T: QKV writes q,k as int8 limbs (+ per-(row,head)
// scale) and v as bf16 planes; attention phase 1 runs on IMMA.
// B=384, S=128, E=512, H=4, D=128, F=2048.
// ---------------------------------------------------------------------------

constexpr int Bb = 384, Ss = 128, Ee = 512, Ff = 2048;
constexpr int MM = Bb * Ss, NQKV = 3 * Ee;

// activations
__device__ int8_t   g_xqh [(size_t)MM * Ee],  g_xql [(size_t)MM * Ee];
__device__ float    g_sx[MM];
__device__ int8_t   g_qk8h[(size_t)MM * 1024], g_qk8l[(size_t)MM * 1024];
__device__ float    g_sqk[(size_t)MM * 8];
__device__ uint16_t g_vph[(size_t)MM * 512],  g_vpl[(size_t)MM * 512];
__device__ float    g_attf[(size_t)MM * Ee];
__device__ int8_t   g_atqh[(size_t)MM * Ee],  g_atql[(size_t)MM * Ee];
__device__ float    g_sat[MM];
__device__ float    g_x1f[(size_t)MM * Ee];
__device__ int8_t   g_x1qh[(size_t)MM * Ee],  g_x1ql[(size_t)MM * Ee];
__device__ float    g_sx1[MM];
__device__ float    g_hf [(size_t)MM * Ff];
__device__ int8_t   g_hqh [(size_t)MM * Ff],  g_hql [(size_t)MM * Ff];
__device__ float    g_sh[MM];
// weights (int8 limbs, [N][K], per-col scale)
__device__ int8_t   g_wqkvqh[(size_t)NQKV * Ee], g_wqkvql[(size_t)NQKV * Ee];
__device__ float    g_swqkv[NQKV];
__device__ int8_t   g_woqh[(size_t)Ee * Ee],  g_woql[(size_t)Ee * Ee];
__device__ float    g_swo[Ee];
__device__ int8_t   g_w1qh[(size_t)Ff * Ee],  g_w1ql[(size_t)Ff * Ee];
__device__ float    g_sw1[Ff];
__device__ int8_t   g_w2qh[(size_t)Ee * Ff],  g_w2ql[(size_t)Ee * Ff];
__device__ float    g_sw2[Ee];
__device__ float    g_bqkv[NQKV];

__device__ __forceinline__ void split2(float v, uint16_t& h, uint16_t& l) {
    float hf;
    asm("cvt.rn.bf16.f32 %0, %1;" : "=h"(h) : "f"(v));
    asm("cvt.f32.bf16 %0, %1;"    : "=f"(hf) : "h"(h));
    asm("cvt.rn.bf16.f32 %0, %1;" : "=h"(l) : "f"(v - hf));
}
__device__ __forceinline__ uint32_t cvta_s(const void* p) {
    uint32_t a;
    asm("{\n\t.reg .u64 t;\n\tcvta.to.shared.u64 t, %1;\n\tcvt.u32.u64 %0, t;\n\t}"
        : "=r"(a) : "l"(p));
    return a;
}
#define CP16(s, g)  asm volatile("cp.async.cg.shared.global [%0], [%1], 16;" ::"r"(s), "l"(g))
#define CPCOMMIT()  asm volatile("cp.async.commit_group;" ::: "memory")
__device__ __forceinline__ void cpwait(int n) {
    if (n >= 2)      asm volatile("cp.async.wait_group 2;" ::: "memory");
    else if (n == 1) asm volatile("cp.async.wait_group 1;" ::: "memory");
    else             asm volatile("cp.async.wait_group 0;" ::: "memory");
}
#define LDSM4(r0, r1, r2, r3, a) \
    asm volatile("ldmatrix.sync.aligned.m8n8.x4.shared.b16 {%0,%1,%2,%3}, [%4];" \
        : "=r"(r0), "=r"(r1), "=r"(r2), "=r"(r3) : "r"(a))
#define LDSM4T(r0, r1, r2, r3, a) \
    asm volatile("ldmatrix.sync.aligned.m8n8.x4.trans.shared.b16 {%0,%1,%2,%3}, [%4];" \
        : "=r"(r0), "=r"(r1), "=r"(r2), "=r"(r3) : "r"(a))
#define STS32(a, v) asm volatile("st.shared.b32 [%0], %1;" ::"r"(a), "r"(v) : "memory")

__device__ __forceinline__ void mma16(float* d, const uint32_t* a,
                                      uint32_t b0, uint32_t b1) {
    asm("mma.sync.aligned.m16n8k16.row.col.f32.bf16.bf16.f32 "
        "{%0,%1,%2,%3}, {%4,%5,%6,%7}, {%8,%9}, {%0,%1,%2,%3};\n"
        : "+f"(d[0]), "+f"(d[1]), "+f"(d[2]), "+f"(d[3])
        : "r"(a[0]), "r"(a[1]), "r"(a[2]), "r"(a[3]), "r"(b0), "r"(b1));
}
__device__ __forceinline__ void mma3(float* d, const uint32_t* ah, const uint32_t* al,
                                     uint32_t bh0, uint32_t bh1,
                                     uint32_t bl0, uint32_t bl1) {
    mma16(d, ah, bh0, bh1);
    mma16(d, al, bh0, bh1);
    mma16(d, ah, bl0, bl1);
}
__device__ __forceinline__ void imma32(int* d, const uint32_t* a,
                                       uint32_t b0, uint32_t b1) {
    asm("mma.sync.aligned.m16n8k32.row.col.s32.s8.s8.s32 "
        "{%0,%1,%2,%3}, {%4,%5,%6,%7}, {%8,%9}, {%0,%1,%2,%3};\n"
        : "+r"(d[0]), "+r"(d[1]), "+r"(d[2]), "+r"(d[3])
        : "r"(a[0]), "r"(a[1]), "r"(a[2]), "r"(a[3]), "r"(b0), "r"(b1));
}
__device__ __forceinline__ void q2limb(float v, float inv, int& h, int& l) {
    const int q = (int)rintf(v * inv);
    h = (q + 128) >> 8;
    l = q - (h << 8);
}

// ---------------------------------------------------------------------------
// prep: bias concat + int8 quant of all weights (per-out-col scale, [N][K])
// ---------------------------------------------------------------------------
__global__ void prep_all(const float* __restrict__ bq, const float* __restrict__ bk,
                         const float* __restrict__ bv,
                         const float* __restrict__ wq, const float* __restrict__ wk,
                         const float* __restrict__ wv, const float* __restrict__ wo,
                         const float* __restrict__ w1, const float* __restrict__ w2) {
    __shared__ uint32_t tile[32][33];
    __shared__ float smax[8][32];
    const int bidx = blockIdx.x;
    const int lx = threadIdx.x & 31, ly = threadIdx.x >> 5;
    if (bidx < 6) {
        const int i = bidx * 256 + threadIdx.x;
        if (i < NQKV)
            g_bqkv[i] = i < 512 ? bq[i] : (i < 1024 ? bk[i - 512] : bv[i - 1024]);
        return;
    }
    const int id = bidx - 6;
    const float* W; int8_t *Qh, *Ql; float* Sd;
    int Nsrc, K, nb, srccol, destrow;
    if (id < 48) {
        nb = id * 32;
        W = nb < 512 ? wq : (nb < 1024 ? wk : wv);
        srccol = nb & 511; destrow = nb;
        Qh = g_wqkvqh; Ql = g_wqkvql; Sd = g_swqkv; Nsrc = 512; K = 512;
    } else if (id < 64) {
        nb = (id - 48) * 32; srccol = nb; destrow = nb;
        W = wo; Qh = g_woqh; Ql = g_woql; Sd = g_swo; Nsrc = 512; K = 512;
    } else if (id < 128) {
        nb = (id - 64) * 32; srccol = nb; destrow = nb;
        W = w1; Qh = g_w1qh; Ql = g_w1ql; Sd = g_sw1; Nsrc = 2048; K = 512;
    } else {
        nb = (id - 128) * 32; srccol = nb; destrow = nb;
        W = w2; Qh = g_w2qh; Ql = g_w2ql; Sd = g_sw2; Nsrc = 512; K = 2048;
    }
    float mx = 0.f;
    for (int k = ly; k < K; k += 8)
        mx = fmaxf(mx, fabsf(W[(size_t)k * Nsrc + srccol + lx]));
    smax[ly][lx] = mx;
    __syncthreads();
    if (ly == 0) {
        for (int i = 1; i < 8; i++) mx = fmaxf(mx, smax[i][lx]);
        const float d = mx > 0.f ? mx * (1.f / 32639.f) : 1.f;
        smax[0][lx] = 1.f / d;
        Sd[destrow + lx] = d;
    }
    __syncthreads();
    const float inv = smax[0][lx];
    for (int kb = 0; kb < K; kb += 32) {
        for (int j = ly; j < 32; j += 8) {
            int h, l;
            q2limb(W[(size_t)(kb + j) * Nsrc + srccol + lx], inv, h, l);
            tile[j][lx] = (uint32_t)(uint8_t)h | ((uint32_t)(uint8_t)l << 8);
        }
        __syncthreads();
        for (int j = ly; j < 32; j += 8) {
            const uint32_t t = tile[lx][j];
            const size_t o = (size_t)(destrow + j) * K + kb + lx;
            Qh[o] = (int8_t)(t & 255);
            Ql[o] = (int8_t)((t >> 8) & 255);
        }
        __syncthreads();
    }
}

// quant_rows: f32 source, per-row scale
template <int KQ>
__global__ __launch_bounds__(256)
void quant_rows(const float* __restrict__ src, int8_t* __restrict__ qh,
                int8_t* __restrict__ ql, float* __restrict__ sc) {
    const int w = threadIdx.x >> 5, lane = threadIdx.x & 31;
    const int row = blockIdx.x * 8 + w;
    const float* s = src + (size_t)row * KQ;
    constexpr int J = KQ / 128;
    float4 v[J];
    float mx = 0.f;
#pragma unroll
    for (int j = 0; j < J; j++) {
        v[j] = *(const float4*)(s + j * 128 + lane * 4);
        mx = fmaxf(mx, fmaxf(fmaxf(fabsf(v[j].x), fabsf(v[j].y)),
                             fmaxf(fabsf(v[j].z), fabsf(v[j].w))));
    }
#pragma unroll
    for (int o = 16; o; o >>= 1) mx = fmaxf(mx, __shfl_xor_sync(0xffffffffu, mx, o));
    const float d = mx > 0.f ? mx * (1.f / 32639.f) : 1.f;
    const float inv = 1.f / d;
    if (lane == 0) sc[row] = d;
#pragma unroll
    for (int j = 0; j < J; j++) {
        int h0, l0, h1, l1, h2, l2, h3, l3;
        q2limb(v[j].x, inv, h0, l0); q2limb(v[j].y, inv, h1, l1);
        q2limb(v[j].z, inv, h2, l2); q2limb(v[j].w, inv, h3, l3);
        *(uint32_t*)(qh + (size_t)row * KQ + j * 128 + lane * 4) =
            (h0 & 255) | ((h1 & 255) << 8) | ((h2 & 255) << 16) | ((h3 & 255) << 24);
        *(uint32_t*)(ql + (size_t)row * KQ + j * 128 + lane * 4) =
            (l0 & 255) | ((l1 & 255) << 8) | ((l2 & 255) << 16) | ((l3 & 255) << 24);
    }
}

// ---------------------------------------------------------------------------
// int8 2-limb GEMM: v = (A@B^T)*sa*sb + bias. Tile 128x128, BK=128, 3-stage,
// 8 warps 2x4 (warp 64x32).
// EPI: 0 relu->f32; 1 +res->f32;
//      2 QKV: blockIdx.x<8 -> q,k int8 limbs + per-(row,head) scale;
//             blockIdx.x>=8 -> v bf16 planes.
// ---------------------------------------------------------------------------
constexpr int I8_STGB = 65536;
constexpr int SMEM_I8 = 3 * I8_STGB;

template <int EPI>
__global__ __launch_bounds__(256, 1)
void gemm_i8(const int8_t* __restrict__ Ah_, const int8_t* __restrict__ Al_,
             const int8_t* __restrict__ Bh_, const int8_t* __restrict__ Bl_,
             const float* __restrict__ sa, const float* __restrict__ sb,
             const float* __restrict__ bias, const float* __restrict__ res,
             float* __restrict__ out,
             uint16_t* __restrict__ Ph, uint16_t* __restrict__ Pl,
             int8_t* __restrict__ Qo_h, int8_t* __restrict__ Qo_l,
             float* __restrict__ sOut, int Nout, int K) {
    extern __shared__ char smraw[];
    const uint32_t sbase = cvta_s(smraw);
    const int tid = threadIdx.x, wid = tid >> 5, lane = tid & 31;
    const int wm = wid >> 2, wn = wid & 3;
    const int mB = blockIdx.y * 128, nB = blockIdx.x * 128;
    const int l7 = lane & 7, l8 = (lane >> 3) & 1, l16 = lane >> 4;

    const int trow = tid >> 3, tch = tid & 7;
    const uint32_t dst0 = trow * 128 + (((uint32_t)tch ^ (trow & 7)) << 4);
    const int8_t* bp[4];
    bp[0] = Ah_ + (size_t)(mB + trow) * K + tch * 16;
    bp[1] = Al_ + (size_t)(mB + trow) * K + tch * 16;
    bp[2] = Bh_ + (size_t)(nB + trow) * K + tch * 16;
    bp[3] = Bl_ + (size_t)(nB + trow) * K + tch * 16;

    int hh[4][4][4], cr[4][4][4];
#pragma unroll
    for (int a = 0; a < 4; a++)
#pragma unroll
        for (int b = 0; b < 4; b++)
#pragma unroll
            for (int c = 0; c < 4; c++) { hh[a][b][c] = 0; cr[a][b][c] = 0; }

    auto issue = [&](int s) {
        const uint32_t stb = sbase + (s % 3) * I8_STGB;
        const int kg = s * 128;
#pragma unroll
        for (int pl = 0; pl < 4; pl++) {
            const int8_t* gp = bp[pl] + kg;
#pragma unroll
            for (int i2 = 0; i2 < 4; i2++)
                CP16(stb + pl * 16384 + dst0 + i2 * 4096, gp + (size_t)i2 * 32 * K);
        }
        CPCOMMIT();
    };

    const int nT = K >> 7;
    issue(0);
    if (nT > 1) issue(1);

    const uint32_t raBase[4] = {
        (uint32_t)(wm * 64 + 0 + l8 * 8 + l7),  (uint32_t)(wm * 64 + 16 + l8 * 8 + l7),
        (uint32_t)(wm * 64 + 32 + l8 * 8 + l7), (uint32_t)(wm * 64 + 48 + l8 * 8 + l7)};
    const uint32_t rbBase[2] = {
        (uint32_t)(wn * 32 + l8 * 8 + l7), (uint32_t)(wn * 32 + 16 + l8 * 8 + l7)};

    for (int t = 0; t < nT; t++) {
        cpwait(t < nT - 1 ? 1 : 0);
        __syncthreads();
        if (t + 2 < nT) issue(t + 2);
        const uint32_t stb = sbase + (t % 3) * I8_STGB;
#pragma unroll
        for (int b = 0; b < 4; b++) {
            uint32_t ahf[4][4], alf[4][4];
#pragma unroll
            for (int mi = 0; mi < 4; mi++) {
                const uint32_t r = raBase[mi];
                const uint32_t base = stb + r * 128;
                const uint32_t ch = (uint32_t)((2 * b + l16) ^ (r & 7)) << 4;
                LDSM4(ahf[mi][0], ahf[mi][1], ahf[mi][2], ahf[mi][3], base + ch);
                LDSM4(alf[mi][0], alf[mi][1], alf[mi][2], alf[mi][3], base + 16384 + ch);
            }
#pragma unroll
            for (int j2 = 0; j2 < 2; j2++) {
                const uint32_t r = rbBase[j2];
                const uint32_t baseB = stb + 32768 + r * 128;
                const uint32_t ch = (uint32_t)((2 * b + l16) ^ (r & 7)) << 4;
                uint32_t bh0, bh1, bh2, bh3, bl0, bl1, bl2, bl3;
                LDSM4(bh0, bh1, bh2, bh3, baseB + ch);
                LDSM4(bl0, bl1, bl2, bl3, baseB + 16384 + ch);
#pragma unroll
                for (int mi = 0; mi < 4; mi++) {
                    imma32(hh[mi][2 * j2],     ahf[mi], bh0, bh2);
                    imma32(hh[mi][2 * j2 + 1], ahf[mi], bh1, bh3);
                }
#pragma unroll
                for (int mi = 0; mi < 4; mi++) {
                    imma32(cr[mi][2 * j2],     ahf[mi], bl0, bl2);
                    imma32(cr[mi][2 * j2 + 1], ahf[mi], bl1, bl3);
                }
#pragma unroll
                for (int mi = 0; mi < 4; mi++) {
                    imma32(cr[mi][2 * j2],     alf[mi], bh0, bh2);
                    imma32(cr[mi][2 * j2 + 1], alf[mi], bh1, bh3);
                }
            }
        }
    }

    if (EPI == 2 && blockIdx.x < 8) {
        // q,k: fused quant, per-(row, 128-col head) scale
        __syncthreads();
        float* rmax = (float*)smraw;           // [128][4]
        const int q4 = lane & 3, g8 = lane >> 2;
#pragma unroll
        for (int mi = 0; mi < 4; mi++) {
            const int lr0 = wm * 64 + mi * 16 + g8;
            const float sa0 = sa[mB + lr0], sa1 = sa[mB + lr0 + 8];
            float m0 = 0.f, m1 = 0.f;
#pragma unroll
            for (int nj = 0; nj < 4; nj++) {
                const int c = nB + wn * 32 + nj * 8 + 2 * q4;
                const float sb0 = sb[c], sb1 = sb[c + 1];
                const float b0 = bias[c], b1v = bias[c + 1];
                const float v0 = ((float)hh[mi][nj][0] * 65536.f + (float)cr[mi][nj][0] * 256.f) * (sa0 * sb0) + b0;
                const float v1 = ((float)hh[mi][nj][1] * 65536.f + (float)cr[mi][nj][1] * 256.f) * (sa0 * sb1) + b1v;
                const float v2 = ((float)hh[mi][nj][2] * 65536.f + (float)cr[mi][nj][2] * 256.f) * (sa1 * sb0) + b0;
                const float v3 = ((float)hh[mi][nj][3] * 65536.f + (float)cr[mi][nj][3] * 256.f) * (sa1 * sb1) + b1v;
                m0 = fmaxf(m0, fmaxf(fabsf(v0), fabsf(v1)));
                m1 = fmaxf(m1, fmaxf(fabsf(v2), fabsf(v3)));
            }
            m0 = fmaxf(m0, __shfl_xor_sync(0xffffffffu, m0, 1));
            m0 = fmaxf(m0, __shfl_xor_sync(0xffffffffu, m0, 2));
            m1 = fmaxf(m1, __shfl_xor_sync(0xffffffffu, m1, 1));
            m1 = fmaxf(m1, __shfl_xor_sync(0xffffffffu, m1, 2));
            if (q4 == 0) {
                rmax[lr0 * 4 + wn] = m0;
                rmax[(lr0 + 8) * 4 + wn] = m1;
            }
        }
        __syncthreads();
#pragma unroll
        for (int mi = 0; mi < 4; mi++) {
            const int lr0 = wm * 64 + mi * 16 + g8;
            const int grow0 = mB + lr0, grow1 = grow0 + 8;
            const float M0 = fmaxf(fmaxf(rmax[lr0 * 4], rmax[lr0 * 4 + 1]),
                                   fmaxf(rmax[lr0 * 4 + 2], rmax[lr0 * 4 + 3]));
            const float M1 = fmaxf(fmaxf(rmax[(lr0 + 8) * 4], rmax[(lr0 + 8) * 4 + 1]),
                                   fmaxf(rmax[(lr0 + 8) * 4 + 2], rmax[(lr0 + 8) * 4 + 3]));
            const float d0 = M0 > 0.f ? M0 * (1.f / 32639.f) : 1.f;
            const float d1 = M1 > 0.f ? M1 * (1.f / 32639.f) : 1.f;
            const float i0 = 1.f / d0, i1 = 1.f / d1;
            if (wn == 0 && q4 == 0) {
                sOut[(size_t)grow0 * 8 + blockIdx.x] = d0;
                sOut[(size_t)grow1 * 8 + blockIdx.x] = d1;
            }
            const float sa0 = sa[grow0], sa1 = sa[grow1];
#pragma unroll
            for (int nj = 0; nj < 4; nj++) {
                const int c = nB + wn * 32 + nj * 8 + 2 * q4;
                const float sb0 = sb[c], sb1 = sb[c + 1];
                const float b0 = bias[c], b1v = bias[c + 1];
                const float v0 = ((float)hh[mi][nj][0] * 65536.f + (float)cr[mi][nj][0] * 256.f) * (sa0 * sb0) + b0;
                const float v1 = ((float)hh[mi][nj][1] * 65536.f + (float)cr[mi][nj][1] * 256.f) * (sa0 * sb1) + b1v;
                const float v2 = ((float)hh[mi][nj][2] * 65536.f + (float)cr[mi][nj][2] * 256.f) * (sa1 * sb0) + b0;
                const float v3 = ((float)hh[mi][nj][3] * 65536.f + (float)cr[mi][nj][3] * 256.f) * (sa1 * sb1) + b1v;
                int h0, l0, h1, l1;
                q2limb(v0, i0, h0, l0); q2limb(v1, i0, h1, l1);
                *(uint16_t*)(Qo_h + (size_t)grow0 * 1024 + c) = (uint16_t)((h0 & 255) | ((h1 & 255) << 8));
                *(uint16_t*)(Qo_l + (size_t)grow0 * 1024 + c) = (uint16_t)((l0 & 255) | ((l1 & 255) << 8));
                q2limb(v2, i1, h0, l0); q2limb(v3, i1, h1, l1);
                *(uint16_t*)(Qo_h + (size_t)grow1 * 1024 + c) = (uint16_t)((h0 & 255) | ((h1 & 255) << 8));
                *(uint16_t*)(Qo_l + (size_t)grow1 * 1024 + c) = (uint16_t)((l0 & 255) | ((l1 & 255) << 8));
            }
        }
    } else {
#pragma unroll
        for (int mi = 0; mi < 4; mi++) {
            const int r0 = mB + wm * 64 + mi * 16 + (lane >> 2);
            const int r1 = r0 + 8;
            const float sa0 = sa[r0], sa1 = sa[r1];
#pragma unroll
            for (int nj = 0; nj < 4; nj++) {
                const int c = nB + wn * 32 + nj * 8 + 2 * (lane & 3);
                const float sb0 = sb[c], sb1 = sb[c + 1];
                const float b0 = bias[c], b1v = bias[c + 1];
                float v0 = ((float)hh[mi][nj][0] * 65536.f + (float)cr[mi][nj][0] * 256.f) * (sa0 * sb0) + b0;
                float v1 = ((float)hh[mi][nj][1] * 65536.f + (float)cr[mi][nj][1] * 256.f) * (sa0 * sb1) + b1v;
                float v2 = ((float)hh[mi][nj][2] * 65536.f + (float)cr[mi][nj][2] * 256.f) * (sa1 * sb0) + b0;
                float v3 = ((float)hh[mi][nj][3] * 65536.f + (float)cr[mi][nj][3] * 256.f) * (sa1 * sb1) + b1v;
                if (EPI == 0) {
                    v0 = fmaxf(v0, 0.f); v1 = fmaxf(v1, 0.f);
                    v2 = fmaxf(v2, 0.f); v3 = fmaxf(v3, 0.f);
                }
                if (EPI == 1) {
                    const float2 rv0 = *(const float2*)(res + (size_t)r0 * Nout + c);
                    const float2 rv1 = *(const float2*)(res + (size_t)r1 * Nout + c);
                    v0 += rv0.x; v1 += rv0.y; v2 += rv1.x; v3 += rv1.y;
                }
                if (EPI == 2) {
                    // v bf16 planes: [MM][512], col = c - 1024
                    const int vc = c - 1024;
                    uint16_t h0, l0, h1, l1;
                    split2(v0, h0, l0); split2(v1, h1, l1);
                    *(uint32_t*)(Ph + (size_t)r0 * 512 + vc) = (uint32_t)h0 | ((uint32_t)h1 << 16);
                    *(uint32_t*)(Pl + (size_t)r0 * 512 + vc) = (uint32_t)l0 | ((uint32_t)l1 << 16);
                    split2(v2, h0, l0); split2(v3, h1, l1);
                    *(uint32_t*)(Ph + (size_t)r1 * 512 + vc) = (uint32_t)h0 | ((uint32_t)h1 << 16);
                    *(uint32_t*)(Pl + (size_t)r1 * 512 + vc) = (uint32_t)l0 | ((uint32_t)l1 << 16);
                } else {
                    *(float2*)(out + (size_t)r0 * Nout + c) = make_float2(v0, v1);
                    *(float2*)(out + (size_t)r1 * Nout + c) = make_float2(v2, v3);
                }
            }
        }
    }
}

// ---------------------------------------------------------------------------
// Attention: QK^T on int8 IMMA (q,k limbs + per-(row,head) scales),
// fp32 softmax, P bf16 planes, P@V bf16x3 (LDSM4T), f32 output.
// smem: Qh8/Ql8/Kh8/Kl8 (4x16KB, reused as PH/PL 2x32KB) + VH/VL (2x32KB).
// ---------------------------------------------------------------------------
constexpr int SMEM_ATTN = 131072;

__global__ __launch_bounds__(256, 1)
void attn_kernel(const int8_t* __restrict__ qk8h, const int8_t* __restrict__ qk8l,
                 const float* __restrict__ sqk,
                 const uint16_t* __restrict__ vph, const uint16_t* __restrict__ vpl,
                 float* __restrict__ Of) {
    extern __shared__ char smraw[];
    const uint32_t sb = cvta_s(smraw);
    const uint32_t QH8 = sb, QL8 = sb + 16384, KH8 = sb + 32768, KL8 = sb + 49152;
    const uint32_t PH = sb, PL = sb + 32768;
    const uint32_t VH = sb + 65536, VL = sb + 98304;
    __shared__ float s_sq[128], s_sk[128];

    const int tid = threadIdx.x, bh = blockIdx.x;
    const int bb = bh >> 2, head = bh & 3;
    const int rowg0 = bb * 128;
    const size_t obase = (size_t)rowg0 * Ee + (size_t)head * 128;

    // load q,k int8 limbs (4 x 1024 chunks)
#pragma unroll
    for (int i = 0; i < 16; i++) {
        const int idx = tid + i * 256;
        const int p = idx >> 10, rem = idx & 1023;
        const int row = rem >> 3, c = rem & 7;
        const int8_t* src = ((p & 1) ? qk8l : qk8h) +
            (size_t)(rowg0 + row) * 1024 + (p >> 1) * 512 + head * 128 + c * 16;
        CP16(sb + p * 16384 + row * 128 + ((uint32_t)(c ^ (row & 7)) << 4), src);
    }
    // load v bf16 planes (2 x 2048 chunks)
#pragma unroll
    for (int i = 0; i < 16; i++) {
        const int idx = tid + i * 256;
        const int p = idx >> 11, rem = idx & 2047;
        const int row = rem >> 4, c = rem & 15;
        const uint16_t* src = (p ? vpl : vph) +
            (size_t)(rowg0 + row) * 512 + head * 128 + c * 8;
        CP16(VH + p * 32768 + row * 256 + ((uint32_t)(c ^ (row & 7)) << 4), src);
    }
    if (tid < 128)       s_sq[tid] = sqk[(size_t)(rowg0 + tid) * 8 + head];
    else                 s_sk[tid - 128] = sqk[(size_t)(rowg0 + tid - 128) * 8 + 4 + head];
    CPCOMMIT();
    cpwait(0);
    __syncthreads();

    const int wid = tid >> 5, lane = tid & 31;
    const int g = lane >> 2, q = lane & 3;
    const int l7 = lane & 7, l8 = (lane >> 3) & 1, l16 = lane >> 4;
    const int rbase = wid * 16;
    const int ra = rbase + l8 * 8 + l7;

    // ---- phase 1: scores = Q @ K^T (int8 2-limb IMMA) ----
    int hh[16][4], cr[16][4];
#pragma unroll
    for (int j = 0; j < 16; j++)
#pragma unroll
        for (int c = 0; c < 4; c++) { hh[j][c] = 0; cr[j][c] = 0; }

#pragma unroll
    for (int b = 0; b < 4; b++) {
        const uint32_t chA = (uint32_t)((2 * b + l16) ^ (ra & 7)) << 4;
        uint32_t ahf[4], alf[4];
        LDSM4(ahf[0], ahf[1], ahf[2], ahf[3], QH8 + ra * 128 + chA);
        LDSM4(alf[0], alf[1], alf[2], alf[3], QL8 + ra * 128 + chA);
#pragma unroll
        for (int j2 = 0; j2 < 8; j2++) {
            const int kr = j2 * 16 + l8 * 8 + l7;
            const uint32_t chB = (uint32_t)((2 * b + l16) ^ (kr & 7)) << 4;
            uint32_t kh0, kh1, kh2, kh3, kl0, kl1, kl2, kl3;
            LDSM4(kh0, kh1, kh2, kh3, KH8 + kr * 128 + chB);
            LDSM4(kl0, kl1, kl2, kl3, KL8 + kr * 128 + chB);
            imma32(hh[2 * j2],     ahf, kh0, kh2);
            imma32(hh[2 * j2 + 1], ahf, kh1, kh3);
            imma32(cr[2 * j2],     ahf, kl0, kl2);
            imma32(cr[2 * j2 + 1], ahf, kl1, kl3);
            imma32(cr[2 * j2],     alf, kh0, kh2);
            imma32(cr[2 * j2 + 1], alf, kh1, kh3);
        }
    }
    __syncthreads();    // all warps done reading Q/K tiles (reused as P below)

    // ---- scores -> fp32 with sq*sk scales ----
    const int pr0 = rbase + g, pr1 = pr0 + 8;
    const float sq0 = s_sq[pr0], sq1 = s_sq[pr1];
    float acc[16][4];
#pragma unroll
    for (int j = 0; j < 16; j++) {
        const float k0 = s_sk[j * 8 + 2 * q], k1 = s_sk[j * 8 + 2 * q + 1];
        acc[j][0] = ((float)hh[j][0] * 65536.f + (float)cr[j][0] * 256.f) * (sq0 * k0);
        acc[j][1] = ((float)hh[j][1] * 65536.f + (float)cr[j][1] * 256.f) * (sq0 * k1);
        acc[j][2] = ((float)hh[j][2] * 65536.f + (float)cr[j][2] * 256.f) * (sq1 * k0);
        acc[j][3] = ((float)hh[j][3] * 65536.f + (float)cr[j][3] * 256.f) * (sq1 * k1);
    }

    // ---- softmax (fp32) ----
    float m0 = -1e30f, m1 = -1e30f;
#pragma unroll
    for (int j = 0; j < 16; j++) {
        m0 = fmaxf(m0, fmaxf(acc[j][0], acc[j][1]));
        m1 = fmaxf(m1, fmaxf(acc[j][2], acc[j][3]));
    }
    m0 = fmaxf(m0, __shfl_xor_sync(0xffffffffu, m0, 1));
    m0 = fmaxf(m0, __shfl_xor_sync(0xffffffffu, m0, 2));
    m1 = fmaxf(m1, __shfl_xor_sync(0xffffffffu, m1, 1));
    m1 = fmaxf(m1, __shfl_xor_sync(0xffffffffu, m1, 2));
    float s0 = 0.f, s1 = 0.f;
#pragma unroll
    for (int j = 0; j < 16; j++) {
        acc[j][0] = expf(acc[j][0] - m0);
        acc[j][1] = expf(acc[j][1] - m0);
        acc[j][2] = expf(acc[j][2] - m1);
        acc[j][3] = expf(acc[j][3] - m1);
        s0 += acc[j][0] + acc[j][1];
        s1 += acc[j][2] + acc[j][3];
    }
    s0 += __shfl_xor_sync(0xffffffffu, s0, 1);
    s0 += __shfl_xor_sync(0xffffffffu, s0, 2);
    s1 += __shfl_xor_sync(0xffffffffu, s1, 1);
    s1 += __shfl_xor_sync(0xffffffffu, s1, 2);
    const float r0s = 1.f / s0, r1s = 1.f / s1;

    // ---- store P bf16 planes into PH/PL (warp-private rows) ----
#pragma unroll
    for (int j = 0; j < 16; j++) {
        const uint32_t off0 = pr0 * 256 + ((uint32_t)(j ^ (pr0 & 7)) << 4) + 4 * q;
        const uint32_t off1 = pr1 * 256 + ((uint32_t)(j ^ (pr1 & 7)) << 4) + 4 * q;
        uint16_t h0, l0, h1, l1;
        split2(acc[j][0] * r0s, h0, l0); split2(acc[j][1] * r0s, h1, l1);
        STS32(PH + off0, (uint32_t)h0 | ((uint32_t)h1 << 16));
        STS32(PL + off0, (uint32_t)l0 | ((uint32_t)l1 << 16));
        split2(acc[j][2] * r1s, h0, l0); split2(acc[j][3] * r1s, h1, l1);
        STS32(PH + off1, (uint32_t)h0 | ((uint32_t)h1 << 16));
        STS32(PL + off1, (uint32_t)l0 | ((uint32_t)l1 << 16));
    }
    __syncwarp();

    // ---- phase 3: out = P @ V (bf16x3, V^T frags via LDSM4T) ----
    float acc2[16][4];
#pragma unroll
    for (int j = 0; j < 16; j++)
#pragma unroll
        for (int c = 0; c < 4; c++) acc2[j][c] = 0.f;

#pragma unroll
    for (int kk = 0; kk < 8; kk++) {
        const uint32_t ca = ((uint32_t)((2 * kk + l16) ^ (ra & 7)) << 4) + ra * 256;
        uint32_t ah[4], al[4];
        LDSM4(ah[0], ah[1], ah[2], ah[3], PH + ca);
        LDSM4(al[0], al[1], al[2], al[3], PL + ca);
        const int krow = kk * 16 + l8 * 8 + l7;
#pragma unroll
        for (int j2 = 0; j2 < 8; j2++) {
            const int cj = j2 * 2 + l16;
            const uint32_t cb = ((uint32_t)(cj ^ (krow & 7)) << 4) + krow * 256;
            uint32_t vh_[4], vl_[4];
            LDSM4T(vh_[0], vh_[1], vh_[2], vh_[3], VH + cb);
            LDSM4T(vl_[0], vl_[1], vl_[2], vl_[3], VL + cb);
            mma3(acc2[j2 * 2],     ah, al, vh_[0], vh_[1], vl_[0], vl_[1]);
            mma3(acc2[j2 * 2 + 1], ah, al, vh_[2], vh_[3], vl_[2], vl_[3]);
        }
    }

    // ---- f32 output ----
#pragma unroll
    for (int j = 0; j < 16; j++) {
        const int c = j * 8 + 2 * q;
        const size_t o0 = obase + (size_t)pr0 * Ee + c;
        const size_t o1 = obase + (size_t)pr1 * Ee + c;
        *(float2*)(Of + o0) = make_float2(acc2[j][0], acc2[j][1]);
        *(float2*)(Of + o1) = make_float2(acc2[j][2], acc2[j][3]);
    }
}

// ---------------------------------------------------------------------------
// launch
// ---------------------------------------------------------------------------
extern "C" void kernel_launch(void* const* d_in, const int* in_sizes, int n_in,
                              void* d_out, int out_size) {
    (void)in_sizes; (void)n_in; (void)out_size;
    const float* x  = (const float*)d_in[0];
    const float* wq = (const float*)d_in[1];
    const float* bq = (const float*)d_in[2];
    const float* wk = (const float*)d_in[3];
    const float* bk = (const float*)d_in[4];
    const float* wv = (const float*)d_in[5];
    const float* bv = (const float*)d_in[6];
    const float* wo = (const float*)d_in[7];
    const float* bo = (const float*)d_in[8];
    const float* w1 = (const float*)d_in[9];
    const float* b1 = (const float*)d_in[10];
    const float* w2 = (const float*)d_in[11];
    const float* b2 = (const float*)d_in[12];
    float* out = (float*)d_out;

    int8_t *xqh, *xql, *qk8h, *qk8l, *atqh, *atql, *x1qh, *x1ql, *hqh, *hql;
    int8_t *wqkvqh, *wqkvql, *woqh, *woql, *w1qh, *w1ql, *w2qh, *w2ql;
    uint16_t *vph, *vpl;
    float *sx, *sqk, *sat, *sx1, *sh, *swqkv, *swo, *sw1, *sw2;
    float *attf, *x1f, *hf, *bqkv;
    cudaGetSymbolAddress((void**)&xqh, g_xqh);     cudaGetSymbolAddress((void**)&xql, g_xql);
    cudaGetSymbolAddress((void**)&sx, g_sx);
    cudaGetSymbolAddress((void**)&qk8h, g_qk8h);   cudaGetSymbolAddress((void**)&qk8l, g_qk8l);
    cudaGetSymbolAddress((void**)&sqk, g_sqk);
    cudaGetSymbolAddress((void**)&vph, g_vph);     cudaGetSymbolAddress((void**)&vpl, g_vpl);
    cudaGetSymbolAddress((void**)&attf, g_attf);
    cudaGetSymbolAddress((void**)&atqh, g_atqh);   cudaGetSymbolAddress((void**)&atql, g_atql);
    cudaGetSymbolAddress((void**)&sat, g_sat);
    cudaGetSymbolAddress((void**)&x1f, g_x1f);
    cudaGetSymbolAddress((void**)&x1qh, g_x1qh);   cudaGetSymbolAddress((void**)&x1ql, g_x1ql);
    cudaGetSymbolAddress((void**)&sx1, g_sx1);
    cudaGetSymbolAddress((void**)&hf, g_hf);
    cudaGetSymbolAddress((void**)&hqh, g_hqh);     cudaGetSymbolAddress((void**)&hql, g_hql);
    cudaGetSymbolAddress((void**)&sh, g_sh);
    cudaGetSymbolAddress((void**)&wqkvqh, g_wqkvqh); cudaGetSymbolAddress((void**)&wqkvql, g_wqkvql);
    cudaGetSymbolAddress((void**)&swqkv, g_swqkv);
    cudaGetSymbolAddress((void**)&woqh, g_woqh);   cudaGetSymbolAddress((void**)&woql, g_woql);
    cudaGetSymbolAddress((void**)&swo, g_swo);
    cudaGetSymbolAddress((void**)&w1qh, g_w1qh);   cudaGetSymbolAddress((void**)&w1ql, g_w1ql);
    cudaGetSymbolAddress((void**)&sw1, g_sw1);
    cudaGetSymbolAddress((void**)&w2qh, g_w2qh);   cudaGetSymbolAddress((void**)&w2ql, g_w2ql);
    cudaGetSymbolAddress((void**)&sw2, g_sw2);
    cudaGetSymbolAddress((void**)&bqkv, g_bqkv);

    cudaFuncSetAttribute(gemm_i8<0>, cudaFuncAttributeMaxDynamicSharedMemorySize, SMEM_I8);
    cudaFuncSetAttribute(gemm_i8<1>, cudaFuncAttributeMaxDynamicSharedMemorySize, SMEM_I8);
    cudaFuncSetAttribute(gemm_i8<2>, cudaFuncAttributeMaxDynamicSharedMemorySize, SMEM_I8);
    cudaFuncSetAttribute(attn_kernel, cudaFuncAttributeMaxDynamicSharedMemorySize, SMEM_ATTN);

    // 0: prep (bias concat + int8 quant of all weights)
    prep_all<<<150, 256>>>(bq, bk, bv, wq, wk, wv, wo, w1, w2);
    // 1: quantize x rows
    quant_rows<Ee><<<MM / 8, 256>>>(x, xqh, xql, sx);
    // 2: fused QKV (int8) -> q,k int8 limbs + v bf16 planes
    gemm_i8<2><<<dim3(12, 384), 256, SMEM_I8>>>(xqh, xql, wqkvqh, wqkvql, sx, swqkv,
                                                bqkv, nullptr, nullptr, vph, vpl,
                                                qk8h, qk8l, sqk, NQKV, Ee);
    // 3: attention (int8 QK^T + bf16 P@V) -> f32
    attn_kernel<<<Bb * 4, 256, SMEM_ATTN>>>(qk8h, qk8l, sqk, vph, vpl, attf);
    // 4: quantize attention rows
    quant_rows<Ee><<<MM / 8, 256>>>(attf, atqh, atql, sat);
    // 5: x1 = x + attn @ wo + bo (int8) -> f32
    gemm_i8<1><<<dim3(4, 384), 256, SMEM_I8>>>(atqh, atql, woqh, woql, sat, swo,
                                               bo, x, x1f, nullptr, nullptr,
                                               nullptr, nullptr, nullptr, Ee, Ee);
    // 6: quantize x1 rows
    quant_rows<Ee><<<MM / 8, 256>>>(x1f, x1qh, x1ql, sx1);
    // 7: h = relu(x1 @ w1 + b1) (int8) -> f32
    gemm_i8<0><<<dim3(16, 384), 256, SMEM_I8>>>(x1qh, x1ql, w1qh, w1ql, sx1, sw1,
                                                b1, nullptr, hf, nullptr, nullptr,
                                                nullptr, nullptr, nullptr, Ff, Ee);
    // 8: quantize h rows
    quant_rows<Ff><<<MM / 8, 256>>>(hf, hqh, hql, sh);
    // 9: out = x1 + h @ w2 + b2 (int8) -> f32
    gemm_i8<1><<<dim3(4, 384), 256, SMEM_I8>>>(hqh, hql, w2qh, w2ql, sh, sw2,
                                               b2, x1f, out, nullptr, nullptr,
                                               nullptr, nullptr, nullptr, Ee, Ff);
}